// round 1
// baseline (speedup 1.0000x reference)
#include <cuda_runtime.h>

// Problem constants
#define BB 4
#define SS 1024
#define DM 1024
#define NH 16
#define HD 64

// Scratch (allocation-free: __device__ globals)
__device__ float g_q[BB*NH*SS*HD];     // [b*16+h][s][d], RoPE applied
__device__ float g_k[BB*NH*SS*HD];
__device__ float g_v[BB*NH*SS*HD];
__device__ float g_attn[BB*SS*DM];     // [b][s][h*64+d]
__device__ float g_cos[SS*32];
__device__ float g_sin[SS*32];

// ---------------- f32x2 packed helpers (sm_100a) ----------------
__device__ __forceinline__ unsigned long long pk(float x, float y) {
    unsigned long long r;
    asm("mov.b64 %0, {%1, %2};" : "=l"(r) : "f"(x), "f"(y));
    return r;
}
__device__ __forceinline__ void upk(unsigned long long v, float& x, float& y) {
    asm("mov.b64 {%0, %1}, %2;" : "=f"(x), "=f"(y) : "l"(v));
}
__device__ __forceinline__ void fma2(unsigned long long& c,
                                     unsigned long long a, unsigned long long b) {
    asm("fma.rn.f32x2 %0, %1, %2, %0;" : "+l"(c) : "l"(a), "l"(b));
}
__device__ __forceinline__ void mul2(unsigned long long& c, unsigned long long a) {
    asm("mul.rn.f32x2 %0, %0, %1;" : "+l"(c) : "l"(a));
}

// ---------------- RoPE table ----------------
__global__ void rope_table_kernel() {
    int idx = blockIdx.x * blockDim.x + threadIdx.x;
    if (idx >= SS * 32) return;
    int pos = idx >> 5;
    int i = idx & 31;
    float inv = powf(10000.0f, -((float)(2 * i)) / 64.0f);
    float t = (float)pos * inv;
    g_cos[idx] = cosf(t);
    g_sin[idx] = sinf(t);
}

// ---------------- SGEMM: C[M,N] = A[M,K] * W[N,K]^T ----------------
// mode 0: plain write to C (row-major). A==nullptr means A=g_attn.
// mode 1: QKV epilogue: scatter to g_q/g_k (with RoPE) and g_v.
__global__ __launch_bounds__(256) void sgemm_kernel(
    const float* __restrict__ A, const float* __restrict__ W,
    float* __restrict__ C, int M, int N, int K, int mode)
{
    __shared__ float As[16][132];
    __shared__ float Bs[16][132];
    const int t  = threadIdx.x;
    const int tx = t & 15;
    const int ty = t >> 4;
    const int rowA0 = blockIdx.y * 128;
    const int colB0 = blockIdx.x * 128;
    const float* Ap = A ? A : g_attn;

    unsigned long long acc[8][4];
#pragma unroll
    for (int i = 0; i < 8; i++)
#pragma unroll
        for (int j = 0; j < 4; j++) acc[i][j] = pk(0.f, 0.f);

    const int ar = t >> 2;        // 0..63
    const int ac = (t & 3) * 4;   // 0,4,8,12

    for (int k0 = 0; k0 < K; k0 += 16) {
        float4 a0 = *(const float4*)&Ap[(size_t)(rowA0 + ar) * K + k0 + ac];
        float4 a1 = *(const float4*)&Ap[(size_t)(rowA0 + ar + 64) * K + k0 + ac];
        float4 b0 = *(const float4*)&W[(size_t)(colB0 + ar) * K + k0 + ac];
        float4 b1 = *(const float4*)&W[(size_t)(colB0 + ar + 64) * K + k0 + ac];
        As[ac + 0][ar] = a0.x; As[ac + 1][ar] = a0.y;
        As[ac + 2][ar] = a0.z; As[ac + 3][ar] = a0.w;
        As[ac + 0][ar + 64] = a1.x; As[ac + 1][ar + 64] = a1.y;
        As[ac + 2][ar + 64] = a1.z; As[ac + 3][ar + 64] = a1.w;
        Bs[ac + 0][ar] = b0.x; Bs[ac + 1][ar] = b0.y;
        Bs[ac + 2][ar] = b0.z; Bs[ac + 3][ar] = b0.w;
        Bs[ac + 0][ar + 64] = b1.x; Bs[ac + 1][ar + 64] = b1.y;
        Bs[ac + 2][ar + 64] = b1.z; Bs[ac + 3][ar + 64] = b1.w;
        __syncthreads();
#pragma unroll
        for (int kk = 0; kk < 16; kk++) {
            ulonglong2 bq0 = *(const ulonglong2*)&Bs[kk][tx * 4];
            ulonglong2 bq1 = *(const ulonglong2*)&Bs[kk][64 + tx * 4];
            unsigned long long b2[4] = {bq0.x, bq0.y, bq1.x, bq1.y};
            float av[8];
#pragma unroll
            for (int i = 0; i < 4; i++) av[i] = As[kk][ty * 4 + i];
#pragma unroll
            for (int i = 0; i < 4; i++) av[4 + i] = As[kk][64 + ty * 4 + i];
#pragma unroll
            for (int i = 0; i < 8; i++) {
                unsigned long long a2 = pk(av[i], av[i]);
                fma2(acc[i][0], a2, b2[0]);
                fma2(acc[i][1], a2, b2[1]);
                fma2(acc[i][2], a2, b2[2]);
                fma2(acc[i][3], a2, b2[3]);
            }
        }
        __syncthreads();
    }

    if (mode == 0) {
#pragma unroll
        for (int i = 0; i < 8; i++) {
            int row = rowA0 + ((i < 4) ? (ty * 4 + i) : (64 + ty * 4 + i - 4));
#pragma unroll
            for (int j = 0; j < 4; j++) {
                int col = colB0 + tx * 4 + (j & 1) * 2 + (j >> 1) * 64;
                float x, y;
                upk(acc[i][j], x, y);
                float2 v = make_float2(x, y);
                *(float2*)&C[(size_t)row * N + col] = v;
            }
        }
    } else {
#pragma unroll
        for (int i = 0; i < 8; i++) {
            int row = rowA0 + ((i < 4) ? (ty * 4 + i) : (64 + ty * 4 + i - 4));
            int b = row >> 10;
            int s = row & 1023;
#pragma unroll
            for (int j = 0; j < 4; j++) {
                int n0 = colB0 + tx * 4 + (j & 1) * 2 + (j >> 1) * 64;
                int part = n0 >> 10;
                int rem = n0 & 1023;
                int h = rem >> 6;
                int d = rem & 63;
                float x, y;
                upk(acc[i][j], x, y);
                int base = ((b * NH + h) << 16) + (s << 6) + d;
                if (part == 2) {
                    g_v[base] = x;
                    g_v[base + 1] = y;
                } else {
                    float co = g_cos[(s << 5) + (d >> 1)];
                    float si = g_sin[(s << 5) + (d >> 1)];
                    float rx = x * co - y * si;
                    float ry = y * co + x * si;
                    if (part == 0) { g_q[base] = rx; g_q[base + 1] = ry; }
                    else           { g_k[base] = rx; g_k[base + 1] = ry; }
                }
            }
        }
    }
}

// ---------------- Flash attention ----------------
// Grid: (qtile=16, bh=64). CTA: 256 threads. 64-row q-tile, 64-col k-tiles.
// Thread (r0=(t/16)*4, c0=(t%16)*4) owns a 4x4 score block and a 4-row x 4-dim O block.
__global__ __launch_bounds__(256) void attn_kernel()
{
    __shared__ float Qts[64 * 64];  // [d][r] (transposed)
    __shared__ float KPs[64 * 64];  // K as [d][j]; reused as P [j][r]
    __shared__ float Vs[64 * 64];   // [j][d]

    const int t  = threadIdx.x;
    const int qt = blockIdx.x;
    const int bh = blockIdx.y;
    const int r0 = (t >> 4) * 4;
    const int c0 = (t & 15) * 4;

    const float* Qg = g_q + bh * 65536 + qt * 4096;
#pragma unroll
    for (int qq = 0; qq < 4; qq++) {
        int f = t + qq * 256;
        int r = f >> 4;
        int d = (f & 15) * 4;
        float4 v = *(const float4*)&Qg[r * 64 + d];
        Qts[(d + 0) * 64 + r] = v.x;
        Qts[(d + 1) * 64 + r] = v.y;
        Qts[(d + 2) * 64 + r] = v.z;
        Qts[(d + 3) * 64 + r] = v.w;
    }

    unsigned long long o2[4][2];
#pragma unroll
    for (int i = 0; i < 4; i++) { o2[i][0] = pk(0.f, 0.f); o2[i][1] = pk(0.f, 0.f); }
    float m[4] = {-1e30f, -1e30f, -1e30f, -1e30f};
    float l[4] = {0.f, 0.f, 0.f, 0.f};

    for (int kt = 0; kt <= qt; kt++) {
        const float* Kg = g_k + bh * 65536 + kt * 4096;
        const float* Vg = g_v + bh * 65536 + kt * 4096;
#pragma unroll
        for (int qq = 0; qq < 4; qq++) {
            int f = t + qq * 256;
            int j = f >> 4;
            int d = (f & 15) * 4;
            float4 kv = *(const float4*)&Kg[j * 64 + d];
            KPs[(d + 0) * 64 + j] = kv.x;
            KPs[(d + 1) * 64 + j] = kv.y;
            KPs[(d + 2) * 64 + j] = kv.z;
            KPs[(d + 3) * 64 + j] = kv.w;
            float4 vv = *(const float4*)&Vg[j * 64 + d];
            *(float4*)&Vs[j * 64 + d] = vv;
        }
        __syncthreads();   // (A) tiles ready (also covers Q on first iter)

        // scores: S = Q K^T (4 rows x 4 cols per thread), f32x2 packed
        unsigned long long s2[4][2];
#pragma unroll
        for (int i = 0; i < 4; i++) { s2[i][0] = pk(0.f, 0.f); s2[i][1] = pk(0.f, 0.f); }
#pragma unroll 16
        for (int d = 0; d < 64; d++) {
            ulonglong2 kp = *(const ulonglong2*)&KPs[d * 64 + c0];
            float4 qv = *(const float4*)&Qts[d * 64 + r0];
            unsigned long long a0 = pk(qv.x, qv.x);
            unsigned long long a1 = pk(qv.y, qv.y);
            unsigned long long a2 = pk(qv.z, qv.z);
            unsigned long long a3 = pk(qv.w, qv.w);
            fma2(s2[0][0], a0, kp.x); fma2(s2[0][1], a0, kp.y);
            fma2(s2[1][0], a1, kp.x); fma2(s2[1][1], a1, kp.y);
            fma2(s2[2][0], a2, kp.x); fma2(s2[2][1], a2, kp.y);
            fma2(s2[3][0], a3, kp.x); fma2(s2[3][1], a3, kp.y);
        }

        float sc[4][4];
#pragma unroll
        for (int i = 0; i < 4; i++) {
            upk(s2[i][0], sc[i][0], sc[i][1]);
            upk(s2[i][1], sc[i][2], sc[i][3]);
#pragma unroll
            for (int j = 0; j < 4; j++) sc[i][j] *= 0.125f;
        }
        if (kt == qt) {
#pragma unroll
            for (int i = 0; i < 4; i++)
#pragma unroll
                for (int j = 0; j < 4; j++)
                    if (c0 + j > r0 + i) sc[i][j] = -1e30f;
        }

        float p[4][4];
#pragma unroll
        for (int i = 0; i < 4; i++) {
            float mt = fmaxf(fmaxf(sc[i][0], sc[i][1]), fmaxf(sc[i][2], sc[i][3]));
            mt = fmaxf(mt, __shfl_xor_sync(0xffffffffu, mt, 1));
            mt = fmaxf(mt, __shfl_xor_sync(0xffffffffu, mt, 2));
            mt = fmaxf(mt, __shfl_xor_sync(0xffffffffu, mt, 4));
            mt = fmaxf(mt, __shfl_xor_sync(0xffffffffu, mt, 8));
            float mn = fmaxf(m[i], mt);
            float alpha = __expf(m[i] - mn);
            m[i] = mn;
            float ls = 0.f;
#pragma unroll
            for (int j = 0; j < 4; j++) { p[i][j] = __expf(sc[i][j] - mn); ls += p[i][j]; }
            ls += __shfl_xor_sync(0xffffffffu, ls, 1);
            ls += __shfl_xor_sync(0xffffffffu, ls, 2);
            ls += __shfl_xor_sync(0xffffffffu, ls, 4);
            ls += __shfl_xor_sync(0xffffffffu, ls, 8);
            l[i] = l[i] * alpha + ls;
            unsigned long long al2 = pk(alpha, alpha);
            mul2(o2[i][0], al2);
            mul2(o2[i][1], al2);
        }

        __syncthreads();   // (B) everyone done reading KPs-as-K
#pragma unroll
        for (int i = 0; i < 4; i++)
#pragma unroll
            for (int j = 0; j < 4; j++)
                KPs[(c0 + j) * 64 + (r0 + i)] = p[i][j];  // P^T: [j][r]
        __syncthreads();   // (C) P visible

        // O += P V (4 rows x 4 dims per thread; dims at c0)
#pragma unroll 16
        for (int j = 0; j < 64; j++) {
            float4 pv = *(const float4*)&KPs[j * 64 + r0];
            ulonglong2 vv = *(const ulonglong2*)&Vs[j * 64 + c0];
            unsigned long long a0 = pk(pv.x, pv.x);
            unsigned long long a1 = pk(pv.y, pv.y);
            unsigned long long a2 = pk(pv.z, pv.z);
            unsigned long long a3 = pk(pv.w, pv.w);
            fma2(o2[0][0], a0, vv.x); fma2(o2[0][1], a0, vv.y);
            fma2(o2[1][0], a1, vv.x); fma2(o2[1][1], a1, vv.y);
            fma2(o2[2][0], a2, vv.x); fma2(o2[2][1], a2, vv.y);
            fma2(o2[3][0], a3, vv.x); fma2(o2[3][1], a3, vv.y);
        }
        __syncthreads();   // (D) safe to overwrite tiles next iter
    }

    const int b = bh >> 4;
    const int h = bh & 15;
#pragma unroll
    for (int i = 0; i < 4; i++) {
        float inv = 1.0f / l[i];
        float x0, x1, x2, x3;
        upk(o2[i][0], x0, x1);
        upk(o2[i][1], x2, x3);
        float4 out = make_float4(x0 * inv, x1 * inv, x2 * inv, x3 * inv);
        int s = qt * 64 + r0 + i;
        *(float4*)&g_attn[(size_t)((b << 10) + s) * 1024 + (h << 6) + c0] = out;
    }
}

// ---------------- launch ----------------
extern "C" void kernel_launch(void* const* d_in, const int* in_sizes, int n_in,
                              void* d_out, int out_size)
{
    const float* hidden = (const float*)d_in[0];
    // d_in[1] = positions (== arange(S), used implicitly), d_in[2] = causal mask (hardcoded)
    const float* Wqkv = (const float*)d_in[3];
    const float* Wout = (const float*)d_in[4];
    float* out = (float*)d_out;

    rope_table_kernel<<<128, 256>>>();
    sgemm_kernel<<<dim3(24, 32), 256>>>(hidden, Wqkv, nullptr, 4096, 3072, 1024, 1);
    attn_kernel<<<dim3(16, 64), 256>>>();
    sgemm_kernel<<<dim3(8, 32), 256>>>(nullptr, Wout, out, 4096, 1024, 1024, 0);
}

// round 3
// speedup vs baseline: 1.5668x; 1.5668x over previous
#include <cuda_runtime.h>
#include <cuda_bf16.h>
#include <cstdint>

#define BB 4
#define SS 1024
#define DM 1024
#define NH 16
#define HD 64

// ---------------- scratch (__device__ globals; no runtime allocation) ----------------
__device__ float g_q[BB*NH*SS*HD];
__device__ float g_k[BB*NH*SS*HD];
__device__ float g_v[BB*NH*SS*HD];
__device__ float g_attn[BB*SS*DM];
__device__ float g_cos[SS*32];
__device__ float g_sin[SS*32];

__device__ __nv_bfloat16 gAh[4194304], gAl[4194304];   // hidden hi/lo
__device__ __nv_bfloat16 gWqh[3145728], gWql[3145728]; // Wqkv hi/lo
__device__ __nv_bfloat16 gWoh[1048576], gWol[1048576]; // Wout hi/lo
__device__ __nv_bfloat16 gXh[4194304], gXl[4194304];   // attn hi/lo

// ---------------- f32x2 helpers (SIMT attention) ----------------
__device__ __forceinline__ unsigned long long pk(float x, float y) {
    unsigned long long r;
    asm("mov.b64 %0, {%1, %2};" : "=l"(r) : "f"(x), "f"(y));
    return r;
}
__device__ __forceinline__ void upk(unsigned long long v, float& x, float& y) {
    asm("mov.b64 {%0, %1}, %2;" : "=f"(x), "=f"(y) : "l"(v));
}
__device__ __forceinline__ void fma2(unsigned long long& c,
                                     unsigned long long a, unsigned long long b) {
    asm("fma.rn.f32x2 %0, %1, %2, %0;" : "+l"(c) : "l"(a), "l"(b));
}
__device__ __forceinline__ void mul2(unsigned long long& c, unsigned long long a) {
    asm("mul.rn.f32x2 %0, %0, %1;" : "+l"(c) : "l"(a));
}

// ---------------- warp-MMA helpers (sm_80+ ISA; legal on compute_100) ----------------
__device__ __forceinline__ uint32_t smem_u32(const void* p) {
    uint32_t a;
    asm("{ .reg .u64 t; cvta.to.shared.u64 t, %1; cvt.u32.u64 %0, t; }" : "=r"(a) : "l"(p));
    return a;
}
__device__ __forceinline__ void cp16(uint32_t so, const void* g) {
    asm volatile("cp.async.cg.shared.global [%0], [%1], 16;" :: "r"(so), "l"(g));
}
__device__ __forceinline__ void ldmat4(uint32_t* r, uint32_t addr) {
    asm volatile("ldmatrix.sync.aligned.m8n8.x4.shared.b16 {%0,%1,%2,%3}, [%4];"
        : "=r"(r[0]), "=r"(r[1]), "=r"(r[2]), "=r"(r[3]) : "r"(addr));
}
__device__ __forceinline__ void mma16816(float* c, const uint32_t* a, uint32_t b0, uint32_t b1) {
    asm volatile("mma.sync.aligned.m16n8k16.row.col.f32.bf16.bf16.f32 "
        "{%0,%1,%2,%3}, {%4,%5,%6,%7}, {%8,%9}, {%0,%1,%2,%3};"
        : "+f"(c[0]), "+f"(c[1]), "+f"(c[2]), "+f"(c[3])
        : "r"(a[0]), "r"(a[1]), "r"(a[2]), "r"(a[3]), "r"(b0), "r"(b1));
}

// ---------------- RoPE table ----------------
__global__ void rope_table_kernel() {
    int idx = blockIdx.x * blockDim.x + threadIdx.x;
    if (idx >= SS * 32) return;
    int pos = idx >> 5;
    int i = idx & 31;
    float inv = powf(10000.0f, -((float)(2 * i)) / 64.0f);
    float t = (float)pos * inv;
    g_cos[idx] = cosf(t);
    g_sin[idx] = sinf(t);
}

// ---------------- fp32 -> (hi,lo) bf16 converter ----------------
__global__ void cvt_kernel(const float* __restrict__ src, int n, int mode) {
    int i = (blockIdx.x * blockDim.x + threadIdx.x) * 4;
    if (i >= n) return;
    const float* s = src ? src : g_attn;
    __nv_bfloat16 *hi, *lo;
    if (mode == 0)      { hi = gAh;  lo = gAl;  }
    else if (mode == 1) { hi = gWqh; lo = gWql; }
    else if (mode == 2) { hi = gWoh; lo = gWol; }
    else                { hi = gXh;  lo = gXl;  }
    float4 v = *(const float4*)&s[i];
    __nv_bfloat16 h0 = __float2bfloat16(v.x);
    __nv_bfloat16 h1 = __float2bfloat16(v.y);
    __nv_bfloat16 h2 = __float2bfloat16(v.z);
    __nv_bfloat16 h3 = __float2bfloat16(v.w);
    __nv_bfloat16 l0 = __float2bfloat16(v.x - __bfloat162float(h0));
    __nv_bfloat16 l1 = __float2bfloat16(v.y - __bfloat162float(h1));
    __nv_bfloat16 l2 = __float2bfloat16(v.z - __bfloat162float(h2));
    __nv_bfloat16 l3 = __float2bfloat16(v.w - __bfloat162float(h3));
    *(__nv_bfloat162*)&hi[i]     = __halves2bfloat162(h0, h1);
    *(__nv_bfloat162*)&hi[i + 2] = __halves2bfloat162(h2, h3);
    *(__nv_bfloat162*)&lo[i]     = __halves2bfloat162(l0, l1);
    *(__nv_bfloat162*)&lo[i + 2] = __halves2bfloat162(l2, l3);
}

// ---------------- split-bf16 HMMA GEMM ----------------
// C[M,N] = A[M,1024] * B[N,1024]^T via Ah*Bh + Ah*Bl + Al*Bh (fp32 accum)
// CTA 128x128, 8 warps (4M x 2N), warp tile 32x64, K-chunk 32, 2-stage cp.async.
// Smem per stage: Ah@0, Al@10240, Bh@20480, Bl@30720; rows 80B stride (conflict-free).
#define GEMM_SMEM (2 * 40960)

__global__ __launch_bounds__(256) void mma_gemm(float* __restrict__ C, int mode)
{
    extern __shared__ __align__(128) char sm[];
    const uint32_t sb = smem_u32(sm);
    const int t = threadIdx.x;
    const int lane = t & 31, warp = t >> 5;
    const int wm = warp & 3, wn = warp >> 2;
    const int rowA0 = blockIdx.y * 128;
    const int colB0 = blockIdx.x * 128;

    const __nv_bfloat16 *Ah, *Al, *Bh, *Bl;
    if (mode == 1) { Ah = gAh; Al = gAl; Bh = gWqh; Bl = gWql; }
    else           { Ah = gXh; Al = gXl; Bh = gWoh; Bl = gWol; }
    const __nv_bfloat16* Abase = Ah + (size_t)rowA0 * 1024;
    const __nv_bfloat16* Albase = Al + (size_t)rowA0 * 1024;
    const __nv_bfloat16* Bbase = Bh + (size_t)colB0 * 1024;
    const __nv_bfloat16* Blbase = Bl + (size_t)colB0 * 1024;

    float acc[2][8][4];
#pragma unroll
    for (int i = 0; i < 2; i++)
#pragma unroll
        for (int j = 0; j < 8; j++)
#pragma unroll
            for (int k = 0; k < 4; k++) acc[i][j][k] = 0.f;

    // per-thread load coords
    const int r0l = t >> 2, cb = t & 3;             // i=0: rows 0..63
    // ldmatrix coords
    const int arow = (lane & 15);
    const int acol8 = (lane >> 4) * 8;
    const int quad = lane >> 3;
    const int brow_in = (quad >> 1) * 8 + (lane & 7);
    const int bcol8 = (quad & 1) * 8;

#define PREFETCH(s) do {                                                        \
    const int _buf = (s) & 1;                                                   \
    const uint32_t _sbuf = sb + _buf * 40960;                                   \
    const int _k0 = (s) * 32;                                                   \
    _Pragma("unroll")                                                           \
    for (int _i = 0; _i < 2; _i++) {                                            \
        const int _row = r0l + _i * 64;                                         \
        const uint32_t _so = _sbuf + _row * 80 + cb * 16;                       \
        const size_t _go = (size_t)_row * 1024 + _k0 + cb * 8;                  \
        cp16(_so,          Abase + _go);                                        \
        cp16(_so + 10240,  Albase + _go);                                       \
        cp16(_so + 20480,  Bbase + _go);                                        \
        cp16(_so + 30720,  Blbase + _go);                                       \
    }                                                                           \
} while (0)

    PREFETCH(0);
    asm volatile("cp.async.commit_group;");

    for (int s = 0; s < 32; s++) {
        if (s + 1 < 32) {
            PREFETCH(s + 1);
            asm volatile("cp.async.commit_group;");
            asm volatile("cp.async.wait_group 1;");
        } else {
            asm volatile("cp.async.wait_group 0;");
        }
        __syncthreads();

        const uint32_t sbuf = sb + (s & 1) * 40960;
#pragma unroll
        for (int kk = 0; kk < 32; kk += 16) {
            uint32_t ah[2][4], al[2][4];
#pragma unroll
            for (int mt = 0; mt < 2; mt++) {
                uint32_t aa = sbuf + (wm * 32 + mt * 16 + arow) * 80 + (kk + acol8) * 2;
                ldmat4(ah[mt], aa);
                ldmat4(al[mt], aa + 10240);
            }
#pragma unroll
            for (int ntp = 0; ntp < 4; ntp++) {
                uint32_t ba = sbuf + 20480 + (wn * 64 + ntp * 16 + brow_in) * 80 + (kk + bcol8) * 2;
                uint32_t bh[4], bl[4];
                ldmat4(bh, ba);
                ldmat4(bl, ba + 10240);
#pragma unroll
                for (int mt = 0; mt < 2; mt++) {
                    float* c0 = acc[mt][2 * ntp];
                    float* c1 = acc[mt][2 * ntp + 1];
                    mma16816(c0, ah[mt], bh[0], bh[1]);
                    mma16816(c0, ah[mt], bl[0], bl[1]);
                    mma16816(c0, al[mt], bh[0], bh[1]);
                    mma16816(c1, ah[mt], bh[2], bh[3]);
                    mma16816(c1, ah[mt], bl[2], bl[3]);
                    mma16816(c1, al[mt], bh[2], bh[3]);
                }
            }
        }
        __syncthreads();
    }

    // ---------------- epilogue ----------------
    const int g = lane >> 2, tq = lane & 3;
#pragma unroll
    for (int mt = 0; mt < 2; mt++) {
#pragma unroll
        for (int nt = 0; nt < 8; nt++) {
            const int col = colB0 + wn * 64 + nt * 8 + tq * 2;
#pragma unroll
            for (int hr = 0; hr < 2; hr++) {
                const int row = rowA0 + wm * 32 + mt * 16 + g + hr * 8;
                const float v0 = acc[mt][nt][hr * 2];
                const float v1 = acc[mt][nt][hr * 2 + 1];
                if (mode == 0) {
                    *(float2*)&C[(size_t)row * 1024 + col] = make_float2(v0, v1);
                } else {
                    const int b = row >> 10, srow = row & 1023;
                    const int part = col >> 10, rem = col & 1023;
                    const int h = rem >> 6, d = rem & 63;
                    const size_t gb = ((size_t)(b * NH + h) << 16) + ((size_t)srow << 6) + d;
                    if (part == 2) {
                        *(float2*)&g_v[gb] = make_float2(v0, v1);
                    } else {
                        const float co = g_cos[(srow << 5) + (d >> 1)];
                        const float si = g_sin[(srow << 5) + (d >> 1)];
                        float2 o = make_float2(v0 * co - v1 * si, v1 * co + v0 * si);
                        if (part == 0) *(float2*)&g_q[gb] = o;
                        else           *(float2*)&g_k[gb] = o;
                    }
                }
            }
        }
    }
#undef PREFETCH
}

// ---------------- Flash attention (SIMT f32x2, unchanged from R1-pass) ----------------
__global__ __launch_bounds__(256) void attn_kernel()
{
    __shared__ float Qts[64 * 64];
    __shared__ float KPs[64 * 64];
    __shared__ float Vs[64 * 64];

    const int t  = threadIdx.x;
    const int qt = blockIdx.x;
    const int bh = blockIdx.y;
    const int r0 = (t >> 4) * 4;
    const int c0 = (t & 15) * 4;

    const float* Qg = g_q + bh * 65536 + qt * 4096;
#pragma unroll
    for (int qq = 0; qq < 4; qq++) {
        int f = t + qq * 256;
        int r = f >> 4;
        int d = (f & 15) * 4;
        float4 v = *(const float4*)&Qg[r * 64 + d];
        Qts[(d + 0) * 64 + r] = v.x;
        Qts[(d + 1) * 64 + r] = v.y;
        Qts[(d + 2) * 64 + r] = v.z;
        Qts[(d + 3) * 64 + r] = v.w;
    }

    unsigned long long o2[4][2];
#pragma unroll
    for (int i = 0; i < 4; i++) { o2[i][0] = pk(0.f, 0.f); o2[i][1] = pk(0.f, 0.f); }
    float m[4] = {-1e30f, -1e30f, -1e30f, -1e30f};
    float l[4] = {0.f, 0.f, 0.f, 0.f};

    for (int kt = 0; kt <= qt; kt++) {
        const float* Kg = g_k + bh * 65536 + kt * 4096;
        const float* Vg = g_v + bh * 65536 + kt * 4096;
#pragma unroll
        for (int qq = 0; qq < 4; qq++) {
            int f = t + qq * 256;
            int j = f >> 4;
            int d = (f & 15) * 4;
            float4 kv = *(const float4*)&Kg[j * 64 + d];
            KPs[(d + 0) * 64 + j] = kv.x;
            KPs[(d + 1) * 64 + j] = kv.y;
            KPs[(d + 2) * 64 + j] = kv.z;
            KPs[(d + 3) * 64 + j] = kv.w;
            float4 vv = *(const float4*)&Vg[j * 64 + d];
            *(float4*)&Vs[j * 64 + d] = vv;
        }
        __syncthreads();

        unsigned long long s2[4][2];
#pragma unroll
        for (int i = 0; i < 4; i++) { s2[i][0] = pk(0.f, 0.f); s2[i][1] = pk(0.f, 0.f); }
#pragma unroll 16
        for (int d = 0; d < 64; d++) {
            ulonglong2 kp = *(const ulonglong2*)&KPs[d * 64 + c0];
            float4 qv = *(const float4*)&Qts[d * 64 + r0];
            unsigned long long a0 = pk(qv.x, qv.x);
            unsigned long long a1 = pk(qv.y, qv.y);
            unsigned long long a2 = pk(qv.z, qv.z);
            unsigned long long a3 = pk(qv.w, qv.w);
            fma2(s2[0][0], a0, kp.x); fma2(s2[0][1], a0, kp.y);
            fma2(s2[1][0], a1, kp.x); fma2(s2[1][1], a1, kp.y);
            fma2(s2[2][0], a2, kp.x); fma2(s2[2][1], a2, kp.y);
            fma2(s2[3][0], a3, kp.x); fma2(s2[3][1], a3, kp.y);
        }

        float sc[4][4];
#pragma unroll
        for (int i = 0; i < 4; i++) {
            upk(s2[i][0], sc[i][0], sc[i][1]);
            upk(s2[i][1], sc[i][2], sc[i][3]);
#pragma unroll
            for (int j = 0; j < 4; j++) sc[i][j] *= 0.125f;
        }
        if (kt == qt) {
#pragma unroll
            for (int i = 0; i < 4; i++)
#pragma unroll
                for (int j = 0; j < 4; j++)
                    if (c0 + j > r0 + i) sc[i][j] = -1e30f;
        }

        float p[4][4];
#pragma unroll
        for (int i = 0; i < 4; i++) {
            float mt = fmaxf(fmaxf(sc[i][0], sc[i][1]), fmaxf(sc[i][2], sc[i][3]));
            mt = fmaxf(mt, __shfl_xor_sync(0xffffffffu, mt, 1));
            mt = fmaxf(mt, __shfl_xor_sync(0xffffffffu, mt, 2));
            mt = fmaxf(mt, __shfl_xor_sync(0xffffffffu, mt, 4));
            mt = fmaxf(mt, __shfl_xor_sync(0xffffffffu, mt, 8));
            float mn = fmaxf(m[i], mt);
            float alpha = __expf(m[i] - mn);
            m[i] = mn;
            float ls = 0.f;
#pragma unroll
            for (int j = 0; j < 4; j++) { p[i][j] = __expf(sc[i][j] - mn); ls += p[i][j]; }
            ls += __shfl_xor_sync(0xffffffffu, ls, 1);
            ls += __shfl_xor_sync(0xffffffffu, ls, 2);
            ls += __shfl_xor_sync(0xffffffffu, ls, 4);
            ls += __shfl_xor_sync(0xffffffffu, ls, 8);
            l[i] = l[i] * alpha + ls;
            unsigned long long al2 = pk(alpha, alpha);
            mul2(o2[i][0], al2);
            mul2(o2[i][1], al2);
        }

        __syncthreads();
#pragma unroll
        for (int i = 0; i < 4; i++)
#pragma unroll
            for (int j = 0; j < 4; j++)
                KPs[(c0 + j) * 64 + (r0 + i)] = p[i][j];
        __syncthreads();

#pragma unroll 16
        for (int j = 0; j < 64; j++) {
            float4 pv = *(const float4*)&KPs[j * 64 + r0];
            ulonglong2 vv = *(const ulonglong2*)&Vs[j * 64 + c0];
            unsigned long long a0 = pk(pv.x, pv.x);
            unsigned long long a1 = pk(pv.y, pv.y);
            unsigned long long a2 = pk(pv.z, pv.z);
            unsigned long long a3 = pk(pv.w, pv.w);
            fma2(o2[0][0], a0, vv.x); fma2(o2[0][1], a0, vv.y);
            fma2(o2[1][0], a1, vv.x); fma2(o2[1][1], a1, vv.y);
            fma2(o2[2][0], a2, vv.x); fma2(o2[2][1], a2, vv.y);
            fma2(o2[3][0], a3, vv.x); fma2(o2[3][1], a3, vv.y);
        }
        __syncthreads();
    }

    const int b = bh >> 4;
    const int h = bh & 15;
#pragma unroll
    for (int i = 0; i < 4; i++) {
        float inv = 1.0f / l[i];
        float x0, x1, x2, x3;
        upk(o2[i][0], x0, x1);
        upk(o2[i][1], x2, x3);
        float4 out = make_float4(x0 * inv, x1 * inv, x2 * inv, x3 * inv);
        int s = qt * 64 + r0 + i;
        *(float4*)&g_attn[(size_t)((b << 10) + s) * 1024 + (h << 6) + c0] = out;
    }
}

// ---------------- launch ----------------
extern "C" void kernel_launch(void* const* d_in, const int* in_sizes, int n_in,
                              void* d_out, int out_size)
{
    const float* hidden = (const float*)d_in[0];
    const float* Wqkv = (const float*)d_in[3];
    const float* Wout = (const float*)d_in[4];
    float* out = (float*)d_out;

    cudaFuncSetAttribute(mma_gemm, cudaFuncAttributeMaxDynamicSharedMemorySize, GEMM_SMEM);

    rope_table_kernel<<<128, 256>>>();
    cvt_kernel<<<4096, 256>>>(hidden, 4194304, 0);
    cvt_kernel<<<3072, 256>>>(Wqkv, 3145728, 1);
    cvt_kernel<<<1024, 256>>>(Wout, 1048576, 2);
    mma_gemm<<<dim3(24, 32), 256, GEMM_SMEM>>>(nullptr, 1);   // QKV + RoPE scatter
    attn_kernel<<<dim3(16, 64), 256>>>();
    cvt_kernel<<<4096, 256>>>(nullptr, 4194304, 3);
    mma_gemm<<<dim3(8, 32), 256, GEMM_SMEM>>>(out, 0);        // out-proj
}

// round 7
// speedup vs baseline: 2.6095x; 1.6655x over previous
#include <cuda_runtime.h>
#include <cuda_bf16.h>
#include <cstdint>

#define BB 4
#define SS 1024
#define DM 1024
#define NH 16
#define HD 64

// ---------------- scratch (__device__ globals; no runtime allocation) ----------------
__device__ float g_cos[SS*32];
__device__ float g_sin[SS*32];

__device__ __nv_bfloat16 gAh[4194304], gAl[4194304];   // hidden hi/lo
__device__ __nv_bfloat16 gWqh[3145728], gWql[3145728]; // Wqkv hi/lo
__device__ __nv_bfloat16 gWoh[1048576], gWol[1048576]; // Wout hi/lo
__device__ __nv_bfloat16 gXh[4194304], gXl[4194304];   // attn output hi/lo

// attention operands, split bf16, [bh][...]
__device__ __nv_bfloat16 gQh[4194304], gQl[4194304];   // [bh][s][64], pre-scaled 0.125, RoPE'd
__device__ __nv_bfloat16 gKh[4194304], gKl[4194304];   // [bh][s][64], RoPE'd
__device__ __nv_bfloat16 gVth[4194304], gVtl[4194304]; // [bh][d][s]  (transposed V)

// ---------------- helpers ----------------
__device__ __forceinline__ uint32_t smem_u32(const void* p) {
    uint32_t a;
    asm("{ .reg .u64 t; cvta.to.shared.u64 t, %1; cvt.u32.u64 %0, t; }" : "=r"(a) : "l"(p));
    return a;
}
__device__ __forceinline__ void cp16(uint32_t so, const void* g) {
    asm volatile("cp.async.cg.shared.global [%0], [%1], 16;" :: "r"(so), "l"(g));
}
__device__ __forceinline__ void ldmat4(uint32_t* r, uint32_t addr) {
    asm volatile("ldmatrix.sync.aligned.m8n8.x4.shared.b16 {%0,%1,%2,%3}, [%4];"
        : "=r"(r[0]), "=r"(r[1]), "=r"(r[2]), "=r"(r[3]) : "r"(addr));
}
__device__ __forceinline__ void mma16816(float* c, const uint32_t* a, uint32_t b0, uint32_t b1) {
    asm volatile("mma.sync.aligned.m16n8k16.row.col.f32.bf16.bf16.f32 "
        "{%0,%1,%2,%3}, {%4,%5,%6,%7}, {%8,%9}, {%0,%1,%2,%3};"
        : "+f"(c[0]), "+f"(c[1]), "+f"(c[2]), "+f"(c[3])
        : "r"(a[0]), "r"(a[1]), "r"(a[2]), "r"(a[3]), "r"(b0), "r"(b1));
}
// pack two floats into bf16x2 (lo = low half)
__device__ __forceinline__ uint32_t pkbf(float lo, float hi) {
    uint32_t r;
    asm("cvt.rn.bf16x2.f32 %0, %1, %2;" : "=r"(r) : "f"(hi), "f"(lo));
    return r;
}
__device__ __forceinline__ float bflo(uint32_t u) { return __uint_as_float(u << 16); }
__device__ __forceinline__ float bfhi(uint32_t u) { return __uint_as_float(u & 0xFFFF0000u); }

// split (v0,v1) into hi/lo bf16x2 words
__device__ __forceinline__ void split2(float v0, float v1, uint32_t& hi, uint32_t& lo) {
    hi = pkbf(v0, v1);
    lo = pkbf(v0 - bflo(hi), v1 - bfhi(hi));
}

// fast exp on FMA/ALU pipes (x <= 0 expected; clamped)
__device__ __forceinline__ float fexp(float x) {
    float y = fmaxf(x, -80.0f) * 1.4426950408889634f;
    float t = y + 12582912.0f;                      // round-to-nearest via magic
    int e = (__float_as_int(t) & 0x7FFFFF) - 0x400000;
    float f = y - (t - 12582912.0f);                // f in [-0.5, 0.5]
    float p =      1.3333558146428443e-3f;
    p = fmaf(p, f, 9.6181291076284772e-3f);
    p = fmaf(p, f, 5.5504108664798463e-2f);
    p = fmaf(p, f, 2.4022650695910072e-1f);
    p = fmaf(p, f, 6.9314718055994531e-1f);
    p = fmaf(p, f, 1.0f);
    return __int_as_float(__float_as_int(p) + (e << 23));
}

// ---------------- RoPE table ----------------
__global__ void rope_table_kernel() {
    int idx = blockIdx.x * blockDim.x + threadIdx.x;
    if (idx >= SS * 32) return;
    int pos = idx >> 5;
    int i = idx & 31;
    float inv = powf(10000.0f, -((float)(2 * i)) / 64.0f);
    float t = (float)pos * inv;
    g_cos[idx] = cosf(t);
    g_sin[idx] = sinf(t);
}

// ---------------- fp32 -> (hi,lo) bf16 converter ----------------
__global__ void cvt_kernel(const float* __restrict__ src, int n, int mode) {
    int i = (blockIdx.x * blockDim.x + threadIdx.x) * 4;
    if (i >= n) return;
    __nv_bfloat16 *hi, *lo;
    if (mode == 0)      { hi = gAh;  lo = gAl;  }
    else if (mode == 1) { hi = gWqh; lo = gWql; }
    else                { hi = gWoh; lo = gWol; }
    float4 v = *(const float4*)&src[i];
    uint32_t h01, l01, h23, l23;
    split2(v.x, v.y, h01, l01);
    split2(v.z, v.w, h23, l23);
    *(uint32_t*)&hi[i]     = h01;
    *(uint32_t*)&hi[i + 2] = h23;
    *(uint32_t*)&lo[i]     = l01;
    *(uint32_t*)&lo[i + 2] = l23;
}

// ---------------- split-bf16 HMMA GEMM (CTA 128x128, 8 warps 32x64, 2-stage) ----------------
#define GEMM_SMEM (2 * 40960)

__global__ __launch_bounds__(256) void mma_gemm(float* __restrict__ C, int mode)
{
    extern __shared__ __align__(128) char sm[];
    const uint32_t sb = smem_u32(sm);
    const int t = threadIdx.x;
    const int lane = t & 31, warp = t >> 5;
    const int wm = warp & 3, wn = warp >> 2;
    const int rowA0 = blockIdx.y * 128;
    const int colB0 = blockIdx.x * 128;

    const __nv_bfloat16 *Ah, *Al, *Bh, *Bl;
    if (mode == 1) { Ah = gAh; Al = gAl; Bh = gWqh; Bl = gWql; }
    else           { Ah = gXh; Al = gXl; Bh = gWoh; Bl = gWol; }
    const __nv_bfloat16* Abase = Ah + (size_t)rowA0 * 1024;
    const __nv_bfloat16* Albase = Al + (size_t)rowA0 * 1024;
    const __nv_bfloat16* Bbase = Bh + (size_t)colB0 * 1024;
    const __nv_bfloat16* Blbase = Bl + (size_t)colB0 * 1024;

    float acc[2][8][4];
#pragma unroll
    for (int i = 0; i < 2; i++)
#pragma unroll
        for (int j = 0; j < 8; j++)
#pragma unroll
            for (int k = 0; k < 4; k++) acc[i][j][k] = 0.f;

    const int r0l = t >> 2, cb = t & 3;
    const int arow = (lane & 15);
    const int acol8 = (lane >> 4) * 8;
    const int quad = lane >> 3;
    const int brow_in = (quad >> 1) * 8 + (lane & 7);
    const int bcol8 = (quad & 1) * 8;

#define PREFETCH(s) do {                                                        \
    const int _buf = (s) & 1;                                                   \
    const uint32_t _sbuf = sb + _buf * 40960;                                   \
    const int _k0 = (s) * 32;                                                   \
    _Pragma("unroll")                                                           \
    for (int _i = 0; _i < 2; _i++) {                                            \
        const int _row = r0l + _i * 64;                                         \
        const uint32_t _so = _sbuf + _row * 80 + cb * 16;                       \
        const size_t _go = (size_t)_row * 1024 + _k0 + cb * 8;                  \
        cp16(_so,          Abase + _go);                                        \
        cp16(_so + 10240,  Albase + _go);                                       \
        cp16(_so + 20480,  Bbase + _go);                                        \
        cp16(_so + 30720,  Blbase + _go);                                       \
    }                                                                           \
} while (0)

    PREFETCH(0);
    asm volatile("cp.async.commit_group;");

    for (int s = 0; s < 32; s++) {
        if (s + 1 < 32) {
            PREFETCH(s + 1);
            asm volatile("cp.async.commit_group;");
            asm volatile("cp.async.wait_group 1;");
        } else {
            asm volatile("cp.async.wait_group 0;");
        }
        __syncthreads();

        const uint32_t sbuf = sb + (s & 1) * 40960;
#pragma unroll
        for (int kk = 0; kk < 32; kk += 16) {
            uint32_t ah[2][4], al[2][4];
#pragma unroll
            for (int mt = 0; mt < 2; mt++) {
                uint32_t aa = sbuf + (wm * 32 + mt * 16 + arow) * 80 + (kk + acol8) * 2;
                ldmat4(ah[mt], aa);
                ldmat4(al[mt], aa + 10240);
            }
#pragma unroll
            for (int ntp = 0; ntp < 4; ntp++) {
                uint32_t ba = sbuf + 20480 + (wn * 64 + ntp * 16 + brow_in) * 80 + (kk + bcol8) * 2;
                uint32_t bh[4], bl[4];
                ldmat4(bh, ba);
                ldmat4(bl, ba + 10240);
#pragma unroll
                for (int mt = 0; mt < 2; mt++) {
                    float* c0 = acc[mt][2 * ntp];
                    float* c1 = acc[mt][2 * ntp + 1];
                    mma16816(c0, ah[mt], bh[0], bh[1]);
                    mma16816(c0, ah[mt], bl[0], bl[1]);
                    mma16816(c0, al[mt], bh[0], bh[1]);
                    mma16816(c1, ah[mt], bh[2], bh[3]);
                    mma16816(c1, ah[mt], bl[2], bl[3]);
                    mma16816(c1, al[mt], bh[2], bh[3]);
                }
            }
        }
        __syncthreads();
    }

    // ---------------- epilogue ----------------
    const int g = lane >> 2, tq = lane & 3;
#pragma unroll
    for (int mt = 0; mt < 2; mt++) {
#pragma unroll
        for (int nt = 0; nt < 8; nt++) {
            const int col = colB0 + wn * 64 + nt * 8 + tq * 2;
#pragma unroll
            for (int hr = 0; hr < 2; hr++) {
                const int row = rowA0 + wm * 32 + mt * 16 + g + hr * 8;
                const float v0 = acc[mt][nt][hr * 2];
                const float v1 = acc[mt][nt][hr * 2 + 1];
                if (mode == 0) {
                    *(float2*)&C[(size_t)row * 1024 + col] = make_float2(v0, v1);
                } else {
                    const int b = row >> 10, srow = row & 1023;
                    const int part = col >> 10, rem = col & 1023;
                    const int h = rem >> 6, d = rem & 63;
                    const size_t bhbase = (size_t)(b * NH + h) << 16;
                    if (part == 2) {
                        // V transposed: [bh][d][s]
                        uint32_t hi, lo;
                        split2(v0, v1, hi, lo);
                        gVth[bhbase + (size_t)d * 1024 + srow]       = __ushort_as_bfloat16((unsigned short)(hi & 0xFFFF));
                        gVth[bhbase + (size_t)(d + 1) * 1024 + srow] = __ushort_as_bfloat16((unsigned short)(hi >> 16));
                        gVtl[bhbase + (size_t)d * 1024 + srow]       = __ushort_as_bfloat16((unsigned short)(lo & 0xFFFF));
                        gVtl[bhbase + (size_t)(d + 1) * 1024 + srow] = __ushort_as_bfloat16((unsigned short)(lo >> 16));
                    } else {
                        const float co = g_cos[(srow << 5) + (d >> 1)];
                        const float si = g_sin[(srow << 5) + (d >> 1)];
                        float o0 = v0 * co - v1 * si;
                        float o1 = v1 * co + v0 * si;
                        const size_t gb = bhbase + ((size_t)srow << 6) + d;
                        uint32_t hi, lo;
                        if (part == 0) {
                            o0 *= 0.125f; o1 *= 0.125f;   // fold softmax scale into Q
                            split2(o0, o1, hi, lo);
                            *(uint32_t*)&gQh[gb] = hi;
                            *(uint32_t*)&gQl[gb] = lo;
                        } else {
                            split2(o0, o1, hi, lo);
                            *(uint32_t*)&gKh[gb] = hi;
                            *(uint32_t*)&gKl[gb] = lo;
                        }
                    }
                }
            }
        }
    }
#undef PREFETCH
}

// ---------------- tensorized flash attention ----------------
// Grid (16 qtiles, 64 bh), 128 threads (4 warps). Warp w: q rows w*16..w*16+15.
// Tiles 64x64. smem: Qh/Ql + double-buffered Kh/Kl/Vth/Vtl, 144B row stride.
#define ATT_SMEM (18432 + 2 * 36864)

__global__ __launch_bounds__(128) void attn_kernel()
{
    extern __shared__ __align__(128) char sm[];
    const uint32_t sb = smem_u32(sm);
    const int t = threadIdx.x, lane = t & 31, w = t >> 5;
    const int qt = blockIdx.x, bh = blockIdx.y;

    const __nv_bfloat16* Qh_p  = gQh  + (size_t)bh * 65536 + qt * 4096;
    const __nv_bfloat16* Ql_p  = gQl  + (size_t)bh * 65536 + qt * 4096;
    const __nv_bfloat16* Kh_b  = gKh  + (size_t)bh * 65536;
    const __nv_bfloat16* Kl_b  = gKl  + (size_t)bh * 65536;
    const __nv_bfloat16* Vth_b = gVth + (size_t)bh * 65536;
    const __nv_bfloat16* Vtl_b = gVtl + (size_t)bh * 65536;

    const int arow = lane & 15, acol8 = (lane >> 4) * 8;
    const int quad = lane >> 3;
    const int brow = (quad >> 1) * 8 + (lane & 7);
    const int bcol8 = (quad & 1) * 8;
    const int g = lane >> 2, tq = lane & 3;
    const int row0 = w * 16 + g;   // row within 64-block

    // ---- issue Q loads (full 2 tiles: 64 rows x 8 chunks of 16B each) ----
#pragma unroll
    for (int i = 0; i < 8; i++) {
        int ch = t + i * 128;            // 0..1023
        int tile = ch >> 9;              // 0=h 1=l
        int r = (ch >> 3) & 63, cbk = ch & 7;
        cp16(sb + tile * 9216 + r * 144 + cbk * 16,
             (tile ? Ql_p : Qh_p) + r * 64 + cbk * 8);
    }
    asm volatile("cp.async.commit_group;");

#define LOAD_STAGE(KT) do {                                                   \
    const uint32_t _st = sb + 18432 + ((KT) & 1) * 36864;                     \
    _Pragma("unroll")                                                         \
    for (int _i = 0; _i < 4; _i++) {                                          \
        int _ch = t + _i * 128;          /* 0..511 */                         \
        int _r = _ch >> 3, _cb = _ch & 7;                                     \
        uint32_t _off = _r * 144 + _cb * 16;                                  \
        size_t _gk = (size_t)(KT) * 4096 + _r * 64 + _cb * 8;                 \
        size_t _gv = (size_t)_r * 1024 + (KT) * 64 + _cb * 8;                 \
        cp16(_st + _off,         Kh_b + _gk);                                 \
        cp16(_st + 9216 + _off,  Kl_b + _gk);                                 \
        cp16(_st + 18432 + _off, Vth_b + _gv);                                \
        cp16(_st + 27648 + _off, Vtl_b + _gv);                                \
    }                                                                         \
} while (0)

    LOAD_STAGE(0);
    asm volatile("cp.async.commit_group;");

    float m0 = -1e30f, m1 = -1e30f, l0 = 0.f, l1 = 0.f;
    float o[8][4];
#pragma unroll
    for (int nt = 0; nt < 8; nt++)
#pragma unroll
        for (int j = 0; j < 4; j++) o[nt][j] = 0.f;
    uint32_t qh[4][4], ql[4][4];

    for (int kt = 0; kt <= qt; kt++) {
        if (kt + 1 <= qt) {
            LOAD_STAGE(kt + 1);
            asm volatile("cp.async.commit_group;");
            asm volatile("cp.async.wait_group 1;");
        } else {
            asm volatile("cp.async.wait_group 0;");
        }
        __syncthreads();

        if (kt == 0) {
#pragma unroll
            for (int c = 0; c < 4; c++) {
                uint32_t qa = sb + (w * 16 + arow) * 144 + (c * 16 + acol8) * 2;
                ldmat4(qh[c], qa);
                ldmat4(ql[c], qa + 9216);
            }
        }

        const uint32_t ST  = sb + 18432 + (kt & 1) * 36864;
        const uint32_t KH = ST, VTH = ST + 18432;

        // ---- scores S = Q K^T (split bf16, 3 products) ----
        float sc[8][4];
#pragma unroll
        for (int nt = 0; nt < 8; nt++)
#pragma unroll
            for (int j = 0; j < 4; j++) sc[nt][j] = 0.f;

#pragma unroll
        for (int np = 0; np < 4; np++) {
#pragma unroll
            for (int c = 0; c < 4; c++) {
                uint32_t kh4[4], kl4[4];
                uint32_t ka = KH + (np * 16 + brow) * 144 + (c * 16 + bcol8) * 2;
                ldmat4(kh4, ka);
                ldmat4(kl4, ka + 9216);
                mma16816(sc[2 * np],     qh[c], kh4[0], kh4[1]);
                mma16816(sc[2 * np],     qh[c], kl4[0], kl4[1]);
                mma16816(sc[2 * np],     ql[c], kh4[0], kh4[1]);
                mma16816(sc[2 * np + 1], qh[c], kh4[2], kh4[3]);
                mma16816(sc[2 * np + 1], qh[c], kl4[2], kl4[3]);
                mma16816(sc[2 * np + 1], ql[c], kh4[2], kh4[3]);
            }
        }

        if (kt == qt) {
#pragma unroll
            for (int nt = 0; nt < 8; nt++) {
                int cbase = nt * 8 + tq * 2;
                if (cbase     > row0)     sc[nt][0] = -1e30f;
                if (cbase + 1 > row0)     sc[nt][1] = -1e30f;
                if (cbase     > row0 + 8) sc[nt][2] = -1e30f;
                if (cbase + 1 > row0 + 8) sc[nt][3] = -1e30f;
            }
        }

        // ---- online softmax (poly exp, no MUFU) ----
        float mt0 = sc[0][0], mt1 = sc[0][2];
#pragma unroll
        for (int nt = 0; nt < 8; nt++) {
            mt0 = fmaxf(mt0, fmaxf(sc[nt][0], sc[nt][1]));
            mt1 = fmaxf(mt1, fmaxf(sc[nt][2], sc[nt][3]));
        }
        mt0 = fmaxf(mt0, __shfl_xor_sync(0xffffffffu, mt0, 1));
        mt0 = fmaxf(mt0, __shfl_xor_sync(0xffffffffu, mt0, 2));
        mt1 = fmaxf(mt1, __shfl_xor_sync(0xffffffffu, mt1, 1));
        mt1 = fmaxf(mt1, __shfl_xor_sync(0xffffffffu, mt1, 2));
        float mn0 = fmaxf(m0, mt0), mn1 = fmaxf(m1, mt1);
        float a0 = fexp(m0 - mn0), a1 = fexp(m1 - mn1);
        m0 = mn0; m1 = mn1;
        float s0 = 0.f, s1 = 0.f;
#pragma unroll
        for (int nt = 0; nt < 8; nt++) {
            sc[nt][0] = fexp(sc[nt][0] - m0); s0 += sc[nt][0];
            sc[nt][1] = fexp(sc[nt][1] - m0); s0 += sc[nt][1];
            sc[nt][2] = fexp(sc[nt][2] - m1); s1 += sc[nt][2];
            sc[nt][3] = fexp(sc[nt][3] - m1); s1 += sc[nt][3];
        }
        s0 += __shfl_xor_sync(0xffffffffu, s0, 1);
        s0 += __shfl_xor_sync(0xffffffffu, s0, 2);
        s1 += __shfl_xor_sync(0xffffffffu, s1, 1);
        s1 += __shfl_xor_sync(0xffffffffu, s1, 2);
        l0 = l0 * a0 + s0;
        l1 = l1 * a1 + s1;
#pragma unroll
        for (int nt = 0; nt < 8; nt++) {
            o[nt][0] *= a0; o[nt][1] *= a0;
            o[nt][2] *= a1; o[nt][3] *= a1;
        }

        // ---- O += P V (P from score regs, split; V^T tiles as B) ----
#pragma unroll
        for (int c = 0; c < 4; c++) {
            const float* pa = sc[2 * c];
            const float* pb = sc[2 * c + 1];
            uint32_t pah[4], pal[4];
            pah[0] = pkbf(pa[0], pa[1]);
            pah[1] = pkbf(pa[2], pa[3]);
            pah[2] = pkbf(pb[0], pb[1]);
            pah[3] = pkbf(pb[2], pb[3]);
            pal[0] = pkbf(pa[0] - bflo(pah[0]), pa[1] - bfhi(pah[0]));
            pal[1] = pkbf(pa[2] - bflo(pah[1]), pa[3] - bfhi(pah[1]));
            pal[2] = pkbf(pb[0] - bflo(pah[2]), pb[1] - bfhi(pah[2]));
            pal[3] = pkbf(pb[2] - bflo(pah[3]), pb[3] - bfhi(pah[3]));
#pragma unroll
            for (int np = 0; np < 4; np++) {
                uint32_t vh4[4], vl4[4];
                uint32_t va = VTH + (np * 16 + brow) * 144 + (c * 16 + bcol8) * 2;
                ldmat4(vh4, va);
                ldmat4(vl4, va + 9216);
                mma16816(o[2 * np],     pah, vh4[0], vh4[1]);
                mma16816(o[2 * np],     pah, vl4[0], vl4[1]);
                mma16816(o[2 * np],     pal, vh4[0], vh4[1]);
                mma16816(o[2 * np + 1], pah, vh4[2], vh4[3]);
                mma16816(o[2 * np + 1], pah, vl4[2], vl4[3]);
                mma16816(o[2 * np + 1], pal, vh4[2], vh4[3]);
            }
        }
        __syncthreads();
    }
#undef LOAD_STAGE

    // ---- epilogue: X = O / l, write split bf16 ----
    const float il0 = 1.0f / l0, il1 = 1.0f / l1;
    const int b = bh >> 4, h = bh & 15;
    const int sr0 = qt * 64 + w * 16 + g;
    const size_t base0 = ((size_t)((b << 10) + sr0)) * 1024 + h * 64;
    const size_t base1 = base0 + 8 * 1024;
#pragma unroll
    for (int nt = 0; nt < 8; nt++) {
        const int d = nt * 8 + tq * 2;
        uint32_t hi, lo;
        split2(o[nt][0] * il0, o[nt][1] * il0, hi, lo);
        *(uint32_t*)&gXh[base0 + d] = hi;
        *(uint32_t*)&gXl[base0 + d] = lo;
        split2(o[nt][2] * il1, o[nt][3] * il1, hi, lo);
        *(uint32_t*)&gXh[base1 + d] = hi;
        *(uint32_t*)&gXl[base1 + d] = lo;
    }
}

// ---------------- launch ----------------
extern "C" void kernel_launch(void* const* d_in, const int* in_sizes, int n_in,
                              void* d_out, int out_size)
{
    const float* hidden = (const float*)d_in[0];
    const float* Wqkv = (const float*)d_in[3];
    const float* Wout = (const float*)d_in[4];
    float* out = (float*)d_out;

    cudaFuncSetAttribute(mma_gemm, cudaFuncAttributeMaxDynamicSharedMemorySize, GEMM_SMEM);
    cudaFuncSetAttribute(attn_kernel, cudaFuncAttributeMaxDynamicSharedMemorySize, ATT_SMEM);

    rope_table_kernel<<<128, 256>>>();
    cvt_kernel<<<4096, 256>>>(hidden, 4194304, 0);
    cvt_kernel<<<3072, 256>>>(Wqkv, 3145728, 1);
    cvt_kernel<<<1024, 256>>>(Wout, 1048576, 2);
    mma_gemm<<<dim3(24, 32), 256, GEMM_SMEM>>>(nullptr, 1);   // QKV + RoPE + split/scatter
    attn_kernel<<<dim3(16, 64), 128, ATT_SMEM>>>();
    mma_gemm<<<dim3(8, 32), 256, GEMM_SMEM>>>(out, 0);        // out-proj
}

// round 8
// speedup vs baseline: 2.7192x; 1.0420x over previous
#include <cuda_runtime.h>
#include <cuda_bf16.h>
#include <cstdint>

#define BB 4
#define SS 1024
#define DM 1024
#define NH 16
#define HD 64

// ---------------- scratch (__device__ globals; no runtime allocation) ----------------
__device__ float g_cos[SS*32];
__device__ float g_sin[SS*32];

__device__ __nv_bfloat16 gAh[4194304], gAl[4194304];   // hidden hi/lo
__device__ __nv_bfloat16 gWqh[3145728], gWql[3145728]; // Wqkv hi/lo
__device__ __nv_bfloat16 gWoh[1048576], gWol[1048576]; // Wout hi/lo
__device__ __nv_bfloat16 gXh[4194304], gXl[4194304];   // attn output hi/lo

// attention operands, split bf16, [bh][...]
__device__ __nv_bfloat16 gQh[4194304], gQl[4194304];   // [bh][s][64], pre-scaled 0.125, RoPE'd
__device__ __nv_bfloat16 gKh[4194304], gKl[4194304];   // [bh][s][64], RoPE'd
__device__ __nv_bfloat16 gVth[4194304], gVtl[4194304]; // [bh][d][s]  (transposed V)

// ---------------- helpers ----------------
__device__ __forceinline__ uint32_t smem_u32(const void* p) {
    uint32_t a;
    asm("{ .reg .u64 t; cvta.to.shared.u64 t, %1; cvt.u32.u64 %0, t; }" : "=r"(a) : "l"(p));
    return a;
}
__device__ __forceinline__ void cp16(uint32_t so, const void* g) {
    asm volatile("cp.async.cg.shared.global [%0], [%1], 16;" :: "r"(so), "l"(g));
}
__device__ __forceinline__ void ldmat4(uint32_t* r, uint32_t addr) {
    asm volatile("ldmatrix.sync.aligned.m8n8.x4.shared.b16 {%0,%1,%2,%3}, [%4];"
        : "=r"(r[0]), "=r"(r[1]), "=r"(r[2]), "=r"(r[3]) : "r"(addr));
}
__device__ __forceinline__ void mma16816(float* c, const uint32_t* a, uint32_t b0, uint32_t b1) {
    asm volatile("mma.sync.aligned.m16n8k16.row.col.f32.bf16.bf16.f32 "
        "{%0,%1,%2,%3}, {%4,%5,%6,%7}, {%8,%9}, {%0,%1,%2,%3};"
        : "+f"(c[0]), "+f"(c[1]), "+f"(c[2]), "+f"(c[3])
        : "r"(a[0]), "r"(a[1]), "r"(a[2]), "r"(a[3]), "r"(b0), "r"(b1));
}
// pack two floats into bf16x2 (lo = low half)
__device__ __forceinline__ uint32_t pkbf(float lo, float hi) {
    uint32_t r;
    asm("cvt.rn.bf16x2.f32 %0, %1, %2;" : "=r"(r) : "f"(hi), "f"(lo));
    return r;
}
__device__ __forceinline__ float bflo(uint32_t u) { return __uint_as_float(u << 16); }
__device__ __forceinline__ float bfhi(uint32_t u) { return __uint_as_float(u & 0xFFFF0000u); }

// split (v0,v1) into hi/lo bf16x2 words
__device__ __forceinline__ void split2(float v0, float v1, uint32_t& hi, uint32_t& lo) {
    hi = pkbf(v0, v1);
    lo = pkbf(v0 - bflo(hi), v1 - bfhi(hi));
}

// fast exp on FMA/ALU pipes (x <= 0 expected; clamped)
__device__ __forceinline__ float fexp(float x) {
    float y = fmaxf(x, -80.0f) * 1.4426950408889634f;
    float t = y + 12582912.0f;                      // round-to-nearest via magic
    int e = (__float_as_int(t) & 0x7FFFFF) - 0x400000;
    float f = y - (t - 12582912.0f);                // f in [-0.5, 0.5]
    float p =      1.3333558146428443e-3f;
    p = fmaf(p, f, 9.6181291076284772e-3f);
    p = fmaf(p, f, 5.5504108664798463e-2f);
    p = fmaf(p, f, 2.4022650695910072e-1f);
    p = fmaf(p, f, 6.9314718055994531e-1f);
    p = fmaf(p, f, 1.0f);
    return __int_as_float(__float_as_int(p) + (e << 23));
}

// ---------------- RoPE table ----------------
__global__ void rope_table_kernel() {
    int idx = blockIdx.x * blockDim.x + threadIdx.x;
    if (idx >= SS * 32) return;
    int pos = idx >> 5;
    int i = idx & 31;
    float inv = powf(10000.0f, -((float)(2 * i)) / 64.0f);
    float t = (float)pos * inv;
    g_cos[idx] = cosf(t);
    g_sin[idx] = sinf(t);
}

// ---------------- fp32 -> (hi,lo) bf16 converter ----------------
__global__ void cvt_kernel(const float* __restrict__ src, int n, int mode) {
    int i = (blockIdx.x * blockDim.x + threadIdx.x) * 4;
    if (i >= n) return;
    __nv_bfloat16 *hi, *lo;
    if (mode == 0)      { hi = gAh;  lo = gAl;  }
    else if (mode == 1) { hi = gWqh; lo = gWql; }
    else                { hi = gWoh; lo = gWol; }
    float4 v = *(const float4*)&src[i];
    uint32_t h01, l01, h23, l23;
    split2(v.x, v.y, h01, l01);
    split2(v.z, v.w, h23, l23);
    *(uint32_t*)&hi[i]     = h01;
    *(uint32_t*)&hi[i + 2] = h23;
    *(uint32_t*)&lo[i]     = l01;
    *(uint32_t*)&lo[i + 2] = l23;
}

// ---------------- split-bf16 HMMA GEMM (CTA 128x128, 8 warps 32x64, 2-stage) ----------------
// __launch_bounds__(256, 2): cap regs at 128 so 2 CTAs co-reside per SM
// (smem 2x80KB = 160KB <= 228KB). 4 warps/SMSP hide LDSM->MMA latency.
#define GEMM_SMEM (2 * 40960)

__global__ __launch_bounds__(256, 2) void mma_gemm(float* __restrict__ C, int mode)
{
    extern __shared__ __align__(128) char sm[];
    const uint32_t sb = smem_u32(sm);
    const int t = threadIdx.x;
    const int lane = t & 31, warp = t >> 5;
    const int wm = warp & 3, wn = warp >> 2;
    const int rowA0 = blockIdx.y * 128;
    const int colB0 = blockIdx.x * 128;

    const __nv_bfloat16 *Ah, *Al, *Bh, *Bl;
    if (mode == 1) { Ah = gAh; Al = gAl; Bh = gWqh; Bl = gWql; }
    else           { Ah = gXh; Al = gXl; Bh = gWoh; Bl = gWol; }
    const __nv_bfloat16* Abase = Ah + (size_t)rowA0 * 1024;
    const __nv_bfloat16* Albase = Al + (size_t)rowA0 * 1024;
    const __nv_bfloat16* Bbase = Bh + (size_t)colB0 * 1024;
    const __nv_bfloat16* Blbase = Bl + (size_t)colB0 * 1024;

    float acc[2][8][4];
#pragma unroll
    for (int i = 0; i < 2; i++)
#pragma unroll
        for (int j = 0; j < 8; j++)
#pragma unroll
            for (int k = 0; k < 4; k++) acc[i][j][k] = 0.f;

    const int r0l = t >> 2, cb = t & 3;
    const int arow = (lane & 15);
    const int acol8 = (lane >> 4) * 8;
    const int quad = lane >> 3;
    const int brow_in = (quad >> 1) * 8 + (lane & 7);
    const int bcol8 = (quad & 1) * 8;

#define PREFETCH(s) do {                                                        \
    const int _buf = (s) & 1;                                                   \
    const uint32_t _sbuf = sb + _buf * 40960;                                   \
    const int _k0 = (s) * 32;                                                   \
    _Pragma("unroll")                                                           \
    for (int _i = 0; _i < 2; _i++) {                                            \
        const int _row = r0l + _i * 64;                                         \
        const uint32_t _so = _sbuf + _row * 80 + cb * 16;                       \
        const size_t _go = (size_t)_row * 1024 + _k0 + cb * 8;                  \
        cp16(_so,          Abase + _go);                                        \
        cp16(_so + 10240,  Albase + _go);                                       \
        cp16(_so + 20480,  Bbase + _go);                                        \
        cp16(_so + 30720,  Blbase + _go);                                       \
    }                                                                           \
} while (0)

    PREFETCH(0);
    asm volatile("cp.async.commit_group;");

    for (int s = 0; s < 32; s++) {
        if (s + 1 < 32) {
            PREFETCH(s + 1);
            asm volatile("cp.async.commit_group;");
            asm volatile("cp.async.wait_group 1;");
        } else {
            asm volatile("cp.async.wait_group 0;");
        }
        __syncthreads();

        const uint32_t sbuf = sb + (s & 1) * 40960;
#pragma unroll
        for (int kk = 0; kk < 32; kk += 16) {
            uint32_t ah[2][4], al[2][4];
#pragma unroll
            for (int mt = 0; mt < 2; mt++) {
                uint32_t aa = sbuf + (wm * 32 + mt * 16 + arow) * 80 + (kk + acol8) * 2;
                ldmat4(ah[mt], aa);
                ldmat4(al[mt], aa + 10240);
            }
#pragma unroll
            for (int ntp = 0; ntp < 4; ntp++) {
                uint32_t ba = sbuf + 20480 + (wn * 64 + ntp * 16 + brow_in) * 80 + (kk + bcol8) * 2;
                uint32_t bh[4], bl[4];
                ldmat4(bh, ba);
                ldmat4(bl, ba + 10240);
#pragma unroll
                for (int mt = 0; mt < 2; mt++) {
                    float* c0 = acc[mt][2 * ntp];
                    float* c1 = acc[mt][2 * ntp + 1];
                    mma16816(c0, ah[mt], bh[0], bh[1]);
                    mma16816(c0, ah[mt], bl[0], bl[1]);
                    mma16816(c0, al[mt], bh[0], bh[1]);
                    mma16816(c1, ah[mt], bh[2], bh[3]);
                    mma16816(c1, ah[mt], bl[2], bl[3]);
                    mma16816(c1, al[mt], bh[2], bh[3]);
                }
            }
        }
        __syncthreads();
    }

    // ---------------- epilogue ----------------
    const int g = lane >> 2, tq = lane & 3;
#pragma unroll
    for (int mt = 0; mt < 2; mt++) {
#pragma unroll
        for (int nt = 0; nt < 8; nt++) {
            const int col = colB0 + wn * 64 + nt * 8 + tq * 2;
#pragma unroll
            for (int hr = 0; hr < 2; hr++) {
                const int row = rowA0 + wm * 32 + mt * 16 + g + hr * 8;
                const float v0 = acc[mt][nt][hr * 2];
                const float v1 = acc[mt][nt][hr * 2 + 1];
                if (mode == 0) {
                    *(float2*)&C[(size_t)row * 1024 + col] = make_float2(v0, v1);
                } else {
                    const int b = row >> 10, srow = row & 1023;
                    const int part = col >> 10, rem = col & 1023;
                    const int h = rem >> 6, d = rem & 63;
                    const size_t bhbase = (size_t)(b * NH + h) << 16;
                    if (part == 2) {
                        // V transposed: [bh][d][s]
                        uint32_t hi, lo;
                        split2(v0, v1, hi, lo);
                        gVth[bhbase + (size_t)d * 1024 + srow]       = __ushort_as_bfloat16((unsigned short)(hi & 0xFFFF));
                        gVth[bhbase + (size_t)(d + 1) * 1024 + srow] = __ushort_as_bfloat16((unsigned short)(hi >> 16));
                        gVtl[bhbase + (size_t)d * 1024 + srow]       = __ushort_as_bfloat16((unsigned short)(lo & 0xFFFF));
                        gVtl[bhbase + (size_t)(d + 1) * 1024 + srow] = __ushort_as_bfloat16((unsigned short)(lo >> 16));
                    } else {
                        const float co = g_cos[(srow << 5) + (d >> 1)];
                        const float si = g_sin[(srow << 5) + (d >> 1)];
                        float o0 = v0 * co - v1 * si;
                        float o1 = v1 * co + v0 * si;
                        const size_t gb = bhbase + ((size_t)srow << 6) + d;
                        uint32_t hi, lo;
                        if (part == 0) {
                            o0 *= 0.125f; o1 *= 0.125f;   // fold softmax scale into Q
                            split2(o0, o1, hi, lo);
                            *(uint32_t*)&gQh[gb] = hi;
                            *(uint32_t*)&gQl[gb] = lo;
                        } else {
                            split2(o0, o1, hi, lo);
                            *(uint32_t*)&gKh[gb] = hi;
                            *(uint32_t*)&gKl[gb] = lo;
                        }
                    }
                }
            }
        }
    }
#undef PREFETCH
}

// ---------------- tensorized flash attention ----------------
// Grid (16 qtiles, 64 bh), 128 threads (4 warps). Warp w: q rows w*16..w*16+15.
// Tiles 64x64. smem: Qh/Ql + double-buffered Kh/Kl/Vth/Vtl, 144B row stride.
#define ATT_SMEM (18432 + 2 * 36864)

__global__ __launch_bounds__(128) void attn_kernel()
{
    extern __shared__ __align__(128) char sm[];
    const uint32_t sb = smem_u32(sm);
    const int t = threadIdx.x, lane = t & 31, w = t >> 5;
    const int qt = blockIdx.x, bh = blockIdx.y;

    const __nv_bfloat16* Qh_p  = gQh  + (size_t)bh * 65536 + qt * 4096;
    const __nv_bfloat16* Ql_p  = gQl  + (size_t)bh * 65536 + qt * 4096;
    const __nv_bfloat16* Kh_b  = gKh  + (size_t)bh * 65536;
    const __nv_bfloat16* Kl_b  = gKl  + (size_t)bh * 65536;
    const __nv_bfloat16* Vth_b = gVth + (size_t)bh * 65536;
    const __nv_bfloat16* Vtl_b = gVtl + (size_t)bh * 65536;

    const int arow = lane & 15, acol8 = (lane >> 4) * 8;
    const int quad = lane >> 3;
    const int brow = (quad >> 1) * 8 + (lane & 7);
    const int bcol8 = (quad & 1) * 8;
    const int g = lane >> 2, tq = lane & 3;
    const int row0 = w * 16 + g;   // row within 64-block

    // ---- issue Q loads (full 2 tiles: 64 rows x 8 chunks of 16B each) ----
#pragma unroll
    for (int i = 0; i < 8; i++) {
        int ch = t + i * 128;            // 0..1023
        int tile = ch >> 9;              // 0=h 1=l
        int r = (ch >> 3) & 63, cbk = ch & 7;
        cp16(sb + tile * 9216 + r * 144 + cbk * 16,
             (tile ? Ql_p : Qh_p) + r * 64 + cbk * 8);
    }
    asm volatile("cp.async.commit_group;");

#define LOAD_STAGE(KT) do {                                                   \
    const uint32_t _st = sb + 18432 + ((KT) & 1) * 36864;                     \
    _Pragma("unroll")                                                         \
    for (int _i = 0; _i < 4; _i++) {                                          \
        int _ch = t + _i * 128;          /* 0..511 */                         \
        int _r = _ch >> 3, _cb = _ch & 7;                                     \
        uint32_t _off = _r * 144 + _cb * 16;                                  \
        size_t _gk = (size_t)(KT) * 4096 + _r * 64 + _cb * 8;                 \
        size_t _gv = (size_t)_r * 1024 + (KT) * 64 + _cb * 8;                 \
        cp16(_st + _off,         Kh_b + _gk);                                 \
        cp16(_st + 9216 + _off,  Kl_b + _gk);                                 \
        cp16(_st + 18432 + _off, Vth_b + _gv);                                \
        cp16(_st + 27648 + _off, Vtl_b + _gv);                                \
    }                                                                         \
} while (0)

    LOAD_STAGE(0);
    asm volatile("cp.async.commit_group;");

    float m0 = -1e30f, m1 = -1e30f, l0 = 0.f, l1 = 0.f;
    float o[8][4];
#pragma unroll
    for (int nt = 0; nt < 8; nt++)
#pragma unroll
        for (int j = 0; j < 4; j++) o[nt][j] = 0.f;
    uint32_t qh[4][4], ql[4][4];

    for (int kt = 0; kt <= qt; kt++) {
        if (kt + 1 <= qt) {
            LOAD_STAGE(kt + 1);
            asm volatile("cp.async.commit_group;");
            asm volatile("cp.async.wait_group 1;");
        } else {
            asm volatile("cp.async.wait_group 0;");
        }
        __syncthreads();

        if (kt == 0) {
#pragma unroll
            for (int c = 0; c < 4; c++) {
                uint32_t qa = sb + (w * 16 + arow) * 144 + (c * 16 + acol8) * 2;
                ldmat4(qh[c], qa);
                ldmat4(ql[c], qa + 9216);
            }
        }

        const uint32_t ST  = sb + 18432 + (kt & 1) * 36864;
        const uint32_t KH = ST, VTH = ST + 18432;

        // ---- scores S = Q K^T (split bf16, 3 products) ----
        float sc[8][4];
#pragma unroll
        for (int nt = 0; nt < 8; nt++)
#pragma unroll
            for (int j = 0; j < 4; j++) sc[nt][j] = 0.f;

#pragma unroll
        for (int np = 0; np < 4; np++) {
#pragma unroll
            for (int c = 0; c < 4; c++) {
                uint32_t kh4[4], kl4[4];
                uint32_t ka = KH + (np * 16 + brow) * 144 + (c * 16 + bcol8) * 2;
                ldmat4(kh4, ka);
                ldmat4(kl4, ka + 9216);
                mma16816(sc[2 * np],     qh[c], kh4[0], kh4[1]);
                mma16816(sc[2 * np],     qh[c], kl4[0], kl4[1]);
                mma16816(sc[2 * np],     ql[c], kh4[0], kh4[1]);
                mma16816(sc[2 * np + 1], qh[c], kh4[2], kh4[3]);
                mma16816(sc[2 * np + 1], qh[c], kl4[2], kl4[3]);
                mma16816(sc[2 * np + 1], ql[c], kh4[2], kh4[3]);
            }
        }

        if (kt == qt) {
#pragma unroll
            for (int nt = 0; nt < 8; nt++) {
                int cbase = nt * 8 + tq * 2;
                if (cbase     > row0)     sc[nt][0] = -1e30f;
                if (cbase + 1 > row0)     sc[nt][1] = -1e30f;
                if (cbase     > row0 + 8) sc[nt][2] = -1e30f;
                if (cbase + 1 > row0 + 8) sc[nt][3] = -1e30f;
            }
        }

        // ---- online softmax (poly exp, no MUFU) ----
        float mt0 = sc[0][0], mt1 = sc[0][2];
#pragma unroll
        for (int nt = 0; nt < 8; nt++) {
            mt0 = fmaxf(mt0, fmaxf(sc[nt][0], sc[nt][1]));
            mt1 = fmaxf(mt1, fmaxf(sc[nt][2], sc[nt][3]));
        }
        mt0 = fmaxf(mt0, __shfl_xor_sync(0xffffffffu, mt0, 1));
        mt0 = fmaxf(mt0, __shfl_xor_sync(0xffffffffu, mt0, 2));
        mt1 = fmaxf(mt1, __shfl_xor_sync(0xffffffffu, mt1, 1));
        mt1 = fmaxf(mt1, __shfl_xor_sync(0xffffffffu, mt1, 2));
        float mn0 = fmaxf(m0, mt0), mn1 = fmaxf(m1, mt1);
        float a0 = fexp(m0 - mn0), a1 = fexp(m1 - mn1);
        m0 = mn0; m1 = mn1;
        float s0 = 0.f, s1 = 0.f;
#pragma unroll
        for (int nt = 0; nt < 8; nt++) {
            sc[nt][0] = fexp(sc[nt][0] - m0); s0 += sc[nt][0];
            sc[nt][1] = fexp(sc[nt][1] - m0); s0 += sc[nt][1];
            sc[nt][2] = fexp(sc[nt][2] - m1); s1 += sc[nt][2];
            sc[nt][3] = fexp(sc[nt][3] - m1); s1 += sc[nt][3];
        }
        s0 += __shfl_xor_sync(0xffffffffu, s0, 1);
        s0 += __shfl_xor_sync(0xffffffffu, s0, 2);
        s1 += __shfl_xor_sync(0xffffffffu, s1, 1);
        s1 += __shfl_xor_sync(0xffffffffu, s1, 2);
        l0 = l0 * a0 + s0;
        l1 = l1 * a1 + s1;
#pragma unroll
        for (int nt = 0; nt < 8; nt++) {
            o[nt][0] *= a0; o[nt][1] *= a0;
            o[nt][2] *= a1; o[nt][3] *= a1;
        }

        // ---- O += P V (P from score regs, split; V^T tiles as B) ----
#pragma unroll
        for (int c = 0; c < 4; c++) {
            const float* pa = sc[2 * c];
            const float* pb = sc[2 * c + 1];
            uint32_t pah[4], pal[4];
            pah[0] = pkbf(pa[0], pa[1]);
            pah[1] = pkbf(pa[2], pa[3]);
            pah[2] = pkbf(pb[0], pb[1]);
            pah[3] = pkbf(pb[2], pb[3]);
            pal[0] = pkbf(pa[0] - bflo(pah[0]), pa[1] - bfhi(pah[0]));
            pal[1] = pkbf(pa[2] - bflo(pah[1]), pa[3] - bfhi(pah[1]));
            pal[2] = pkbf(pb[0] - bflo(pah[2]), pb[1] - bfhi(pah[2]));
            pal[3] = pkbf(pb[2] - bflo(pah[3]), pb[3] - bfhi(pah[3]));
#pragma unroll
            for (int np = 0; np < 4; np++) {
                uint32_t vh4[4], vl4[4];
                uint32_t va = VTH + (np * 16 + brow) * 144 + (c * 16 + bcol8) * 2;
                ldmat4(vh4, va);
                ldmat4(vl4, va + 9216);
                mma16816(o[2 * np],     pah, vh4[0], vh4[1]);
                mma16816(o[2 * np],     pah, vl4[0], vl4[1]);
                mma16816(o[2 * np],     pal, vh4[0], vh4[1]);
                mma16816(o[2 * np + 1], pah, vh4[2], vh4[3]);
                mma16816(o[2 * np + 1], pah, vl4[2], vl4[3]);
                mma16816(o[2 * np + 1], pal, vh4[2], vh4[3]);
            }
        }
        __syncthreads();
    }
#undef LOAD_STAGE

    // ---- epilogue: X = O / l, write split bf16 ----
    const float il0 = 1.0f / l0, il1 = 1.0f / l1;
    const int b = bh >> 4, h = bh & 15;
    const int sr0 = qt * 64 + w * 16 + g;
    const size_t base0 = ((size_t)((b << 10) + sr0)) * 1024 + h * 64;
    const size_t base1 = base0 + 8 * 1024;
#pragma unroll
    for (int nt = 0; nt < 8; nt++) {
        const int d = nt * 8 + tq * 2;
        uint32_t hi, lo;
        split2(o[nt][0] * il0, o[nt][1] * il0, hi, lo);
        *(uint32_t*)&gXh[base0 + d] = hi;
        *(uint32_t*)&gXl[base0 + d] = lo;
        split2(o[nt][2] * il1, o[nt][3] * il1, hi, lo);
        *(uint32_t*)&gXh[base1 + d] = hi;
        *(uint32_t*)&gXl[base1 + d] = lo;
    }
}

// ---------------- launch ----------------
extern "C" void kernel_launch(void* const* d_in, const int* in_sizes, int n_in,
                              void* d_out, int out_size)
{
    const float* hidden = (const float*)d_in[0];
    const float* Wqkv = (const float*)d_in[3];
    const float* Wout = (const float*)d_in[4];
    float* out = (float*)d_out;

    cudaFuncSetAttribute(mma_gemm, cudaFuncAttributeMaxDynamicSharedMemorySize, GEMM_SMEM);
    cudaFuncSetAttribute(attn_kernel, cudaFuncAttributeMaxDynamicSharedMemorySize, ATT_SMEM);

    rope_table_kernel<<<128, 256>>>();
    cvt_kernel<<<4096, 256>>>(hidden, 4194304, 0);
    cvt_kernel<<<3072, 256>>>(Wqkv, 3145728, 1);
    cvt_kernel<<<1024, 256>>>(Wout, 1048576, 2);
    mma_gemm<<<dim3(24, 32), 256, GEMM_SMEM>>>(nullptr, 1);   // QKV + RoPE + split/scatter
    attn_kernel<<<dim3(16, 64), 128, ATT_SMEM>>>();
    mma_gemm<<<dim3(8, 32), 256, GEMM_SMEM>>>(out, 0);        // out-proj
}

// round 9
// speedup vs baseline: 3.1634x; 1.1634x over previous
#include <cuda_runtime.h>
#include <cuda_bf16.h>
#include <cuda_fp16.h>
#include <cstdint>

#define BB 4
#define SS 1024
#define DM 1024
#define NH 16
#define HD 64

// ---------------- scratch (__device__ globals; no runtime allocation) ----------------
__device__ float g_cos[SS*32];
__device__ float g_sin[SS*32];

__device__ __half gA16h[4194304], gA16l[4194304];      // hidden hi/lo fp16
__device__ __half gW16[3145728];                       // Wqkv fp16 (hi only)
__device__ __nv_bfloat16 gWoh[1048576], gWol[1048576]; // Wout hi/lo bf16
__device__ __nv_bfloat16 gXh[4194304], gXl[4194304];   // attn output hi/lo bf16

// attention operands, split bf16, [bh][...]
__device__ __nv_bfloat16 gQh[4194304], gQl[4194304];   // [bh][s][64], pre-scaled 0.125, RoPE'd
__device__ __nv_bfloat16 gKh[4194304], gKl[4194304];   // [bh][s][64], RoPE'd
__device__ __nv_bfloat16 gVth[4194304], gVtl[4194304]; // [bh][d][s]  (transposed V)

// ---------------- helpers ----------------
__device__ __forceinline__ uint32_t smem_u32(const void* p) {
    uint32_t a;
    asm("{ .reg .u64 t; cvta.to.shared.u64 t, %1; cvt.u32.u64 %0, t; }" : "=r"(a) : "l"(p));
    return a;
}
__device__ __forceinline__ void cp16(uint32_t so, const void* g) {
    asm volatile("cp.async.cg.shared.global [%0], [%1], 16;" :: "r"(so), "l"(g));
}
__device__ __forceinline__ void ldmat4(uint32_t* r, uint32_t addr) {
    asm volatile("ldmatrix.sync.aligned.m8n8.x4.shared.b16 {%0,%1,%2,%3}, [%4];"
        : "=r"(r[0]), "=r"(r[1]), "=r"(r[2]), "=r"(r[3]) : "r"(addr));
}
__device__ __forceinline__ void mma16816(float* c, const uint32_t* a, uint32_t b0, uint32_t b1) {
    asm volatile("mma.sync.aligned.m16n8k16.row.col.f32.bf16.bf16.f32 "
        "{%0,%1,%2,%3}, {%4,%5,%6,%7}, {%8,%9}, {%0,%1,%2,%3};"
        : "+f"(c[0]), "+f"(c[1]), "+f"(c[2]), "+f"(c[3])
        : "r"(a[0]), "r"(a[1]), "r"(a[2]), "r"(a[3]), "r"(b0), "r"(b1));
}
__device__ __forceinline__ void mma16816h(float* c, const uint32_t* a, uint32_t b0, uint32_t b1) {
    asm volatile("mma.sync.aligned.m16n8k16.row.col.f32.f16.f16.f32 "
        "{%0,%1,%2,%3}, {%4,%5,%6,%7}, {%8,%9}, {%0,%1,%2,%3};"
        : "+f"(c[0]), "+f"(c[1]), "+f"(c[2]), "+f"(c[3])
        : "r"(a[0]), "r"(a[1]), "r"(a[2]), "r"(a[3]), "r"(b0), "r"(b1));
}
// pack two floats into bf16x2 (lo = low half)
__device__ __forceinline__ uint32_t pkbf(float lo, float hi) {
    uint32_t r;
    asm("cvt.rn.bf16x2.f32 %0, %1, %2;" : "=r"(r) : "f"(hi), "f"(lo));
    return r;
}
__device__ __forceinline__ float bflo(uint32_t u) { return __uint_as_float(u << 16); }
__device__ __forceinline__ float bfhi(uint32_t u) { return __uint_as_float(u & 0xFFFF0000u); }

// split (v0,v1) into hi/lo bf16x2 words
__device__ __forceinline__ void split2(float v0, float v1, uint32_t& hi, uint32_t& lo) {
    hi = pkbf(v0, v1);
    lo = pkbf(v0 - bflo(hi), v1 - bfhi(hi));
}

// fast exp on FMA/ALU pipes (x <= 0 expected; clamped)
__device__ __forceinline__ float fexp(float x) {
    float y = fmaxf(x, -80.0f) * 1.4426950408889634f;
    float t = y + 12582912.0f;                      // round-to-nearest via magic
    int e = (__float_as_int(t) & 0x7FFFFF) - 0x400000;
    float f = y - (t - 12582912.0f);                // f in [-0.5, 0.5]
    float p =      1.3333558146428443e-3f;
    p = fmaf(p, f, 9.6181291076284772e-3f);
    p = fmaf(p, f, 5.5504108664798463e-2f);
    p = fmaf(p, f, 2.4022650695910072e-1f);
    p = fmaf(p, f, 6.9314718055994531e-1f);
    p = fmaf(p, f, 1.0f);
    return __int_as_float(__float_as_int(p) + (e << 23));
}

// ---------------- RoPE table ----------------
__global__ void rope_table_kernel() {
    int idx = blockIdx.x * blockDim.x + threadIdx.x;
    if (idx >= SS * 32) return;
    int pos = idx >> 5;
    int i = idx & 31;
    float inv = powf(10000.0f, -((float)(2 * i)) / 64.0f);
    float t = (float)pos * inv;
    g_cos[idx] = cosf(t);
    g_sin[idx] = sinf(t);
}

// ---------------- fp32 -> fp16 converters ----------------
// mode 0: hidden -> gA16h/gA16l (split). mode 1: Wqkv -> gW16 (hi only).
__global__ void cvt16_kernel(const float* __restrict__ src, int n, int mode) {
    int i = (blockIdx.x * blockDim.x + threadIdx.x) * 4;
    if (i >= n) return;
    float4 v = *(const float4*)&src[i];
    __half h0 = __float2half_rn(v.x), h1 = __float2half_rn(v.y);
    __half h2 = __float2half_rn(v.z), h3 = __float2half_rn(v.w);
    if (mode == 0) {
        *(__half2*)&gA16h[i]     = __halves2half2(h0, h1);
        *(__half2*)&gA16h[i + 2] = __halves2half2(h2, h3);
        __half l0 = __float2half_rn(v.x - __half2float(h0));
        __half l1 = __float2half_rn(v.y - __half2float(h1));
        __half l2 = __float2half_rn(v.z - __half2float(h2));
        __half l3 = __float2half_rn(v.w - __half2float(h3));
        *(__half2*)&gA16l[i]     = __halves2half2(l0, l1);
        *(__half2*)&gA16l[i + 2] = __halves2half2(l2, l3);
    } else {
        *(__half2*)&gW16[i]     = __halves2half2(h0, h1);
        *(__half2*)&gW16[i + 2] = __halves2half2(h2, h3);
    }
}

// ---------------- fp32 -> (hi,lo) bf16 converter (Wout only) ----------------
__global__ void cvt_kernel(const float* __restrict__ src, int n) {
    int i = (blockIdx.x * blockDim.x + threadIdx.x) * 4;
    if (i >= n) return;
    float4 v = *(const float4*)&src[i];
    uint32_t h01, l01, h23, l23;
    split2(v.x, v.y, h01, l01);
    split2(v.z, v.w, h23, l23);
    *(uint32_t*)&gWoh[i]     = h01;
    *(uint32_t*)&gWoh[i + 2] = h23;
    *(uint32_t*)&gWol[i]     = l01;
    *(uint32_t*)&gWol[i + 2] = l23;
}

// ---------------- QKV GEMM: fp16 2-product (A split, B single) ----------------
// C = (Ah+Al) * Bh^T. CTA 128x128, 8 warps 32x64, K-chunk 32, 2-stage.
// Stage smem: Ah@0, Al@10240, Bh@20480 (80B row stride). 2 buffers x 30720.
#define QKV_SMEM (2 * 30720)

__global__ __launch_bounds__(256, 2) void qkv_gemm()
{
    extern __shared__ __align__(128) char sm[];
    const uint32_t sb = smem_u32(sm);
    const int t = threadIdx.x;
    const int lane = t & 31, warp = t >> 5;
    const int wm = warp & 3, wn = warp >> 2;
    const int rowA0 = blockIdx.y * 128;
    const int colB0 = blockIdx.x * 128;

    const __half* Abase  = gA16h + (size_t)rowA0 * 1024;
    const __half* Albase = gA16l + (size_t)rowA0 * 1024;
    const __half* Bbase  = gW16  + (size_t)colB0 * 1024;

    float acc[2][8][4];
#pragma unroll
    for (int i = 0; i < 2; i++)
#pragma unroll
        for (int j = 0; j < 8; j++)
#pragma unroll
            for (int k = 0; k < 4; k++) acc[i][j][k] = 0.f;

    const int r0l = t >> 2, cb = t & 3;
    const int arow = (lane & 15);
    const int acol8 = (lane >> 4) * 8;
    const int quad = lane >> 3;
    const int brow_in = (quad >> 1) * 8 + (lane & 7);
    const int bcol8 = (quad & 1) * 8;

#define QPREFETCH(s) do {                                                       \
    const uint32_t _sbuf = sb + ((s) & 1) * 30720;                              \
    const int _k0 = (s) * 32;                                                   \
    _Pragma("unroll")                                                           \
    for (int _i = 0; _i < 2; _i++) {                                            \
        const int _row = r0l + _i * 64;                                         \
        const uint32_t _so = _sbuf + _row * 80 + cb * 16;                       \
        const size_t _go = (size_t)_row * 1024 + _k0 + cb * 8;                  \
        cp16(_so,          Abase + _go);                                        \
        cp16(_so + 10240,  Albase + _go);                                       \
        cp16(_so + 20480,  Bbase + _go);                                        \
    }                                                                           \
} while (0)

    QPREFETCH(0);
    asm volatile("cp.async.commit_group;");

    for (int s = 0; s < 32; s++) {
        if (s + 1 < 32) {
            QPREFETCH(s + 1);
            asm volatile("cp.async.commit_group;");
            asm volatile("cp.async.wait_group 1;");
        } else {
            asm volatile("cp.async.wait_group 0;");
        }
        __syncthreads();

        const uint32_t sbuf = sb + (s & 1) * 30720;
#pragma unroll
        for (int kk = 0; kk < 32; kk += 16) {
            uint32_t ah[2][4], al[2][4];
#pragma unroll
            for (int mt = 0; mt < 2; mt++) {
                uint32_t aa = sbuf + (wm * 32 + mt * 16 + arow) * 80 + (kk + acol8) * 2;
                ldmat4(ah[mt], aa);
                ldmat4(al[mt], aa + 10240);
            }
#pragma unroll
            for (int ntp = 0; ntp < 4; ntp++) {
                uint32_t ba = sbuf + 20480 + (wn * 64 + ntp * 16 + brow_in) * 80 + (kk + bcol8) * 2;
                uint32_t bh[4];
                ldmat4(bh, ba);
#pragma unroll
                for (int mt = 0; mt < 2; mt++) {
                    float* c0 = acc[mt][2 * ntp];
                    float* c1 = acc[mt][2 * ntp + 1];
                    mma16816h(c0, ah[mt], bh[0], bh[1]);
                    mma16816h(c0, al[mt], bh[0], bh[1]);
                    mma16816h(c1, ah[mt], bh[2], bh[3]);
                    mma16816h(c1, al[mt], bh[2], bh[3]);
                }
            }
        }
        __syncthreads();
    }

    // ---------------- epilogue: RoPE + split-bf16 scatter ----------------
    const int g = lane >> 2, tq = lane & 3;
#pragma unroll
    for (int mt = 0; mt < 2; mt++) {
#pragma unroll
        for (int nt = 0; nt < 8; nt++) {
            const int col = colB0 + wn * 64 + nt * 8 + tq * 2;
#pragma unroll
            for (int hr = 0; hr < 2; hr++) {
                const int row = rowA0 + wm * 32 + mt * 16 + g + hr * 8;
                const float v0 = acc[mt][nt][hr * 2];
                const float v1 = acc[mt][nt][hr * 2 + 1];
                const int b = row >> 10, srow = row & 1023;
                const int part = col >> 10, rem = col & 1023;
                const int h = rem >> 6, d = rem & 63;
                const size_t bhbase = (size_t)(b * NH + h) << 16;
                if (part == 2) {
                    uint32_t hi, lo;
                    split2(v0, v1, hi, lo);
                    gVth[bhbase + (size_t)d * 1024 + srow]       = __ushort_as_bfloat16((unsigned short)(hi & 0xFFFF));
                    gVth[bhbase + (size_t)(d + 1) * 1024 + srow] = __ushort_as_bfloat16((unsigned short)(hi >> 16));
                    gVtl[bhbase + (size_t)d * 1024 + srow]       = __ushort_as_bfloat16((unsigned short)(lo & 0xFFFF));
                    gVtl[bhbase + (size_t)(d + 1) * 1024 + srow] = __ushort_as_bfloat16((unsigned short)(lo >> 16));
                } else {
                    const float co = g_cos[(srow << 5) + (d >> 1)];
                    const float si = g_sin[(srow << 5) + (d >> 1)];
                    float o0 = v0 * co - v1 * si;
                    float o1 = v1 * co + v0 * si;
                    const size_t gb = bhbase + ((size_t)srow << 6) + d;
                    uint32_t hi, lo;
                    if (part == 0) {
                        o0 *= 0.125f; o1 *= 0.125f;
                        split2(o0, o1, hi, lo);
                        *(uint32_t*)&gQh[gb] = hi;
                        *(uint32_t*)&gQl[gb] = lo;
                    } else {
                        split2(o0, o1, hi, lo);
                        *(uint32_t*)&gKh[gb] = hi;
                        *(uint32_t*)&gKl[gb] = lo;
                    }
                }
            }
        }
    }
#undef QPREFETCH
}

// ---------------- out-proj GEMM: split-bf16 3-product (unchanged) ----------------
#define GEMM_SMEM (2 * 40960)

__global__ __launch_bounds__(256, 2) void mma_gemm(float* __restrict__ C)
{
    extern __shared__ __align__(128) char sm[];
    const uint32_t sb = smem_u32(sm);
    const int t = threadIdx.x;
    const int lane = t & 31, warp = t >> 5;
    const int wm = warp & 3, wn = warp >> 2;
    const int rowA0 = blockIdx.y * 128;
    const int colB0 = blockIdx.x * 128;

    const __nv_bfloat16* Abase  = gXh + (size_t)rowA0 * 1024;
    const __nv_bfloat16* Albase = gXl + (size_t)rowA0 * 1024;
    const __nv_bfloat16* Bbase  = gWoh + (size_t)colB0 * 1024;
    const __nv_bfloat16* Blbase = gWol + (size_t)colB0 * 1024;

    float acc[2][8][4];
#pragma unroll
    for (int i = 0; i < 2; i++)
#pragma unroll
        for (int j = 0; j < 8; j++)
#pragma unroll
            for (int k = 0; k < 4; k++) acc[i][j][k] = 0.f;

    const int r0l = t >> 2, cb = t & 3;
    const int arow = (lane & 15);
    const int acol8 = (lane >> 4) * 8;
    const int quad = lane >> 3;
    const int brow_in = (quad >> 1) * 8 + (lane & 7);
    const int bcol8 = (quad & 1) * 8;

#define PREFETCH(s) do {                                                        \
    const uint32_t _sbuf = sb + ((s) & 1) * 40960;                              \
    const int _k0 = (s) * 32;                                                   \
    _Pragma("unroll")                                                           \
    for (int _i = 0; _i < 2; _i++) {                                            \
        const int _row = r0l + _i * 64;                                         \
        const uint32_t _so = _sbuf + _row * 80 + cb * 16;                       \
        const size_t _go = (size_t)_row * 1024 + _k0 + cb * 8;                  \
        cp16(_so,          Abase + _go);                                        \
        cp16(_so + 10240,  Albase + _go);                                      \
        cp16(_so + 20480,  Bbase + _go);                                        \
        cp16(_so + 30720,  Blbase + _go);                                       \
    }                                                                           \
} while (0)

    PREFETCH(0);
    asm volatile("cp.async.commit_group;");

    for (int s = 0; s < 32; s++) {
        if (s + 1 < 32) {
            PREFETCH(s + 1);
            asm volatile("cp.async.commit_group;");
            asm volatile("cp.async.wait_group 1;");
        } else {
            asm volatile("cp.async.wait_group 0;");
        }
        __syncthreads();

        const uint32_t sbuf = sb + (s & 1) * 40960;
#pragma unroll
        for (int kk = 0; kk < 32; kk += 16) {
            uint32_t ah[2][4], al[2][4];
#pragma unroll
            for (int mt = 0; mt < 2; mt++) {
                uint32_t aa = sbuf + (wm * 32 + mt * 16 + arow) * 80 + (kk + acol8) * 2;
                ldmat4(ah[mt], aa);
                ldmat4(al[mt], aa + 10240);
            }
#pragma unroll
            for (int ntp = 0; ntp < 4; ntp++) {
                uint32_t ba = sbuf + 20480 + (wn * 64 + ntp * 16 + brow_in) * 80 + (kk + bcol8) * 2;
                uint32_t bh[4], bl[4];
                ldmat4(bh, ba);
                ldmat4(bl, ba + 10240);
#pragma unroll
                for (int mt = 0; mt < 2; mt++) {
                    float* c0 = acc[mt][2 * ntp];
                    float* c1 = acc[mt][2 * ntp + 1];
                    mma16816(c0, ah[mt], bh[0], bh[1]);
                    mma16816(c0, ah[mt], bl[0], bl[1]);
                    mma16816(c0, al[mt], bh[0], bh[1]);
                    mma16816(c1, ah[mt], bh[2], bh[3]);
                    mma16816(c1, ah[mt], bl[2], bl[3]);
                    mma16816(c1, al[mt], bh[2], bh[3]);
                }
            }
        }
        __syncthreads();
    }

    const int g = lane >> 2, tq = lane & 3;
#pragma unroll
    for (int mt = 0; mt < 2; mt++) {
#pragma unroll
        for (int nt = 0; nt < 8; nt++) {
            const int col = colB0 + wn * 64 + nt * 8 + tq * 2;
#pragma unroll
            for (int hr = 0; hr < 2; hr++) {
                const int row = rowA0 + wm * 32 + mt * 16 + g + hr * 8;
                *(float2*)&C[(size_t)row * 1024 + col] =
                    make_float2(acc[mt][nt][hr * 2], acc[mt][nt][hr * 2 + 1]);
            }
        }
    }
#undef PREFETCH
}

// ---------------- tensorized flash attention (unchanged) ----------------
#define ATT_SMEM (18432 + 2 * 36864)

__global__ __launch_bounds__(128) void attn_kernel()
{
    extern __shared__ __align__(128) char sm[];
    const uint32_t sb = smem_u32(sm);
    const int t = threadIdx.x, lane = t & 31, w = t >> 5;
    const int qt = blockIdx.x, bh = blockIdx.y;

    const __nv_bfloat16* Qh_p  = gQh  + (size_t)bh * 65536 + qt * 4096;
    const __nv_bfloat16* Ql_p  = gQl  + (size_t)bh * 65536 + qt * 4096;
    const __nv_bfloat16* Kh_b  = gKh  + (size_t)bh * 65536;
    const __nv_bfloat16* Kl_b  = gKl  + (size_t)bh * 65536;
    const __nv_bfloat16* Vth_b = gVth + (size_t)bh * 65536;
    const __nv_bfloat16* Vtl_b = gVtl + (size_t)bh * 65536;

    const int arow = lane & 15, acol8 = (lane >> 4) * 8;
    const int quad = lane >> 3;
    const int brow = (quad >> 1) * 8 + (lane & 7);
    const int bcol8 = (quad & 1) * 8;
    const int g = lane >> 2, tq = lane & 3;
    const int row0 = w * 16 + g;

#pragma unroll
    for (int i = 0; i < 8; i++) {
        int ch = t + i * 128;
        int tile = ch >> 9;
        int r = (ch >> 3) & 63, cbk = ch & 7;
        cp16(sb + tile * 9216 + r * 144 + cbk * 16,
             (tile ? Ql_p : Qh_p) + r * 64 + cbk * 8);
    }
    asm volatile("cp.async.commit_group;");

#define LOAD_STAGE(KT) do {                                                   \
    const uint32_t _st = sb + 18432 + ((KT) & 1) * 36864;                     \
    _Pragma("unroll")                                                         \
    for (int _i = 0; _i < 4; _i++) {                                          \
        int _ch = t + _i * 128;                                               \
        int _r = _ch >> 3, _cb = _ch & 7;                                     \
        uint32_t _off = _r * 144 + _cb * 16;                                  \
        size_t _gk = (size_t)(KT) * 4096 + _r * 64 + _cb * 8;                 \
        size_t _gv = (size_t)_r * 1024 + (KT) * 64 + _cb * 8;                 \
        cp16(_st + _off,         Kh_b + _gk);                                 \
        cp16(_st + 9216 + _off,  Kl_b + _gk);                                 \
        cp16(_st + 18432 + _off, Vth_b + _gv);                                \
        cp16(_st + 27648 + _off, Vtl_b + _gv);                                \
    }                                                                         \
} while (0)

    LOAD_STAGE(0);
    asm volatile("cp.async.commit_group;");

    float m0 = -1e30f, m1 = -1e30f, l0 = 0.f, l1 = 0.f;
    float o[8][4];
#pragma unroll
    for (int nt = 0; nt < 8; nt++)
#pragma unroll
        for (int j = 0; j < 4; j++) o[nt][j] = 0.f;
    uint32_t qh[4][4], ql[4][4];

    for (int kt = 0; kt <= qt; kt++) {
        if (kt + 1 <= qt) {
            LOAD_STAGE(kt + 1);
            asm volatile("cp.async.commit_group;");
            asm volatile("cp.async.wait_group 1;");
        } else {
            asm volatile("cp.async.wait_group 0;");
        }
        __syncthreads();

        if (kt == 0) {
#pragma unroll
            for (int c = 0; c < 4; c++) {
                uint32_t qa = sb + (w * 16 + arow) * 144 + (c * 16 + acol8) * 2;
                ldmat4(qh[c], qa);
                ldmat4(ql[c], qa + 9216);
            }
        }

        const uint32_t ST  = sb + 18432 + (kt & 1) * 36864;
        const uint32_t KH = ST, VTH = ST + 18432;

        float sc[8][4];
#pragma unroll
        for (int nt = 0; nt < 8; nt++)
#pragma unroll
            for (int j = 0; j < 4; j++) sc[nt][j] = 0.f;

#pragma unroll
        for (int np = 0; np < 4; np++) {
#pragma unroll
            for (int c = 0; c < 4; c++) {
                uint32_t kh4[4], kl4[4];
                uint32_t ka = KH + (np * 16 + brow) * 144 + (c * 16 + bcol8) * 2;
                ldmat4(kh4, ka);
                ldmat4(kl4, ka + 9216);
                mma16816(sc[2 * np],     qh[c], kh4[0], kh4[1]);
                mma16816(sc[2 * np],     qh[c], kl4[0], kl4[1]);
                mma16816(sc[2 * np],     ql[c], kh4[0], kh4[1]);
                mma16816(sc[2 * np + 1], qh[c], kh4[2], kh4[3]);
                mma16816(sc[2 * np + 1], qh[c], kl4[2], kl4[3]);
                mma16816(sc[2 * np + 1], ql[c], kh4[2], kh4[3]);
            }
        }

        if (kt == qt) {
#pragma unroll
            for (int nt = 0; nt < 8; nt++) {
                int cbase = nt * 8 + tq * 2;
                if (cbase     > row0)     sc[nt][0] = -1e30f;
                if (cbase + 1 > row0)     sc[nt][1] = -1e30f;
                if (cbase     > row0 + 8) sc[nt][2] = -1e30f;
                if (cbase + 1 > row0 + 8) sc[nt][3] = -1e30f;
            }
        }

        float mt0 = sc[0][0], mt1 = sc[0][2];
#pragma unroll
        for (int nt = 0; nt < 8; nt++) {
            mt0 = fmaxf(mt0, fmaxf(sc[nt][0], sc[nt][1]));
            mt1 = fmaxf(mt1, fmaxf(sc[nt][2], sc[nt][3]));
        }
        mt0 = fmaxf(mt0, __shfl_xor_sync(0xffffffffu, mt0, 1));
        mt0 = fmaxf(mt0, __shfl_xor_sync(0xffffffffu, mt0, 2));
        mt1 = fmaxf(mt1, __shfl_xor_sync(0xffffffffu, mt1, 1));
        mt1 = fmaxf(mt1, __shfl_xor_sync(0xffffffffu, mt1, 2));
        float mn0 = fmaxf(m0, mt0), mn1 = fmaxf(m1, mt1);
        float a0 = fexp(m0 - mn0), a1 = fexp(m1 - mn1);
        m0 = mn0; m1 = mn1;
        float s0 = 0.f, s1 = 0.f;
#pragma unroll
        for (int nt = 0; nt < 8; nt++) {
            sc[nt][0] = fexp(sc[nt][0] - m0); s0 += sc[nt][0];
            sc[nt][1] = fexp(sc[nt][1] - m0); s0 += sc[nt][1];
            sc[nt][2] = fexp(sc[nt][2] - m1); s1 += sc[nt][2];
            sc[nt][3] = fexp(sc[nt][3] - m1); s1 += sc[nt][3];
        }
        s0 += __shfl_xor_sync(0xffffffffu, s0, 1);
        s0 += __shfl_xor_sync(0xffffffffu, s0, 2);
        s1 += __shfl_xor_sync(0xffffffffu, s1, 1);
        s1 += __shfl_xor_sync(0xffffffffu, s1, 2);
        l0 = l0 * a0 + s0;
        l1 = l1 * a1 + s1;
#pragma unroll
        for (int nt = 0; nt < 8; nt++) {
            o[nt][0] *= a0; o[nt][1] *= a0;
            o[nt][2] *= a1; o[nt][3] *= a1;
        }

#pragma unroll
        for (int c = 0; c < 4; c++) {
            const float* pa = sc[2 * c];
            const float* pb = sc[2 * c + 1];
            uint32_t pah[4], pal[4];
            pah[0] = pkbf(pa[0], pa[1]);
            pah[1] = pkbf(pa[2], pa[3]);
            pah[2] = pkbf(pb[0], pb[1]);
            pah[3] = pkbf(pb[2], pb[3]);
            pal[0] = pkbf(pa[0] - bflo(pah[0]), pa[1] - bfhi(pah[0]));
            pal[1] = pkbf(pa[2] - bflo(pah[1]), pa[3] - bfhi(pah[1]));
            pal[2] = pkbf(pb[0] - bflo(pah[2]), pb[1] - bfhi(pah[2]));
            pal[3] = pkbf(pb[2] - bflo(pah[3]), pb[3] - bfhi(pah[3]));
#pragma unroll
            for (int np = 0; np < 4; np++) {
                uint32_t vh4[4], vl4[4];
                uint32_t va = VTH + (np * 16 + brow) * 144 + (c * 16 + bcol8) * 2;
                ldmat4(vh4, va);
                ldmat4(vl4, va + 9216);
                mma16816(o[2 * np],     pah, vh4[0], vh4[1]);
                mma16816(o[2 * np],     pah, vl4[0], vl4[1]);
                mma16816(o[2 * np],     pal, vh4[0], vh4[1]);
                mma16816(o[2 * np + 1], pah, vh4[2], vh4[3]);
                mma16816(o[2 * np + 1], pah, vl4[2], vl4[3]);
                mma16816(o[2 * np + 1], pal, vh4[2], vh4[3]);
            }
        }
        __syncthreads();
    }
#undef LOAD_STAGE

    const float il0 = 1.0f / l0, il1 = 1.0f / l1;
    const int b = bh >> 4, h = bh & 15;
    const int sr0 = qt * 64 + w * 16 + g;
    const size_t base0 = ((size_t)((b << 10) + sr0)) * 1024 + h * 64;
    const size_t base1 = base0 + 8 * 1024;
#pragma unroll
    for (int nt = 0; nt < 8; nt++) {
        const int d = nt * 8 + tq * 2;
        uint32_t hi, lo;
        split2(o[nt][0] * il0, o[nt][1] * il0, hi, lo);
        *(uint32_t*)&gXh[base0 + d] = hi;
        *(uint32_t*)&gXl[base0 + d] = lo;
        split2(o[nt][2] * il1, o[nt][3] * il1, hi, lo);
        *(uint32_t*)&gXh[base1 + d] = hi;
        *(uint32_t*)&gXl[base1 + d] = lo;
    }
}

// ---------------- launch ----------------
extern "C" void kernel_launch(void* const* d_in, const int* in_sizes, int n_in,
                              void* d_out, int out_size)
{
    const float* hidden = (const float*)d_in[0];
    const float* Wqkv = (const float*)d_in[3];
    const float* Wout = (const float*)d_in[4];
    float* out = (float*)d_out;

    cudaFuncSetAttribute(qkv_gemm, cudaFuncAttributeMaxDynamicSharedMemorySize, QKV_SMEM);
    cudaFuncSetAttribute(mma_gemm, cudaFuncAttributeMaxDynamicSharedMemorySize, GEMM_SMEM);
    cudaFuncSetAttribute(attn_kernel, cudaFuncAttributeMaxDynamicSharedMemorySize, ATT_SMEM);

    rope_table_kernel<<<128, 256>>>();                      // launch 0
    cvt16_kernel<<<4096, 256>>>(hidden, 4194304, 0);        // launch 1
    cvt16_kernel<<<3072, 256>>>(Wqkv, 3145728, 1);          // launch 2
    qkv_gemm<<<dim3(24, 32), 256, QKV_SMEM>>>();            // launch 3 (ncu slot)
    cvt_kernel<<<1024, 256>>>(Wout, 1048576);               // launch 4
    attn_kernel<<<dim3(16, 64), 128, ATT_SMEM>>>();         // launch 5
    mma_gemm<<<dim3(8, 32), 256, GEMM_SMEM>>>(out);         // launch 6
}

// round 10
// speedup vs baseline: 3.3574x; 1.0613x over previous
#include <cuda_runtime.h>
#include <cuda_bf16.h>
#include <cuda_fp16.h>
#include <cstdint>

#define BB 4
#define SS 1024
#define DM 1024
#define NH 16
#define HD 64

// ---------------- scratch (__device__ globals; no runtime allocation) ----------------
__device__ float g_cos[SS*32];
__device__ float g_sin[SS*32];

__device__ __half gA16h[4194304], gA16l[4194304];      // hidden hi/lo fp16
__device__ __half gW16[3145728];                       // Wqkv fp16 (hi only)
__device__ __half gWo16[1048576];                      // Wout fp16 (hi only)
__device__ __half gX16h[4194304], gX16l[4194304];      // attn output hi/lo fp16

// attention operands, split bf16, [bh][...]
__device__ __nv_bfloat16 gQh[4194304], gQl[4194304];   // [bh][s][64], pre-scaled 0.125, RoPE'd
__device__ __nv_bfloat16 gKh[4194304], gKl[4194304];   // [bh][s][64], RoPE'd
__device__ __nv_bfloat16 gVth[4194304], gVtl[4194304]; // [bh][d][s]  (transposed V)

// ---------------- helpers ----------------
__device__ __forceinline__ uint32_t smem_u32(const void* p) {
    uint32_t a;
    asm("{ .reg .u64 t; cvta.to.shared.u64 t, %1; cvt.u32.u64 %0, t; }" : "=r"(a) : "l"(p));
    return a;
}
__device__ __forceinline__ void cp16(uint32_t so, const void* g) {
    asm volatile("cp.async.cg.shared.global [%0], [%1], 16;" :: "r"(so), "l"(g));
}
__device__ __forceinline__ void ldmat4(uint32_t* r, uint32_t addr) {
    asm volatile("ldmatrix.sync.aligned.m8n8.x4.shared.b16 {%0,%1,%2,%3}, [%4];"
        : "=r"(r[0]), "=r"(r[1]), "=r"(r[2]), "=r"(r[3]) : "r"(addr));
}
__device__ __forceinline__ void mma16816(float* c, const uint32_t* a, uint32_t b0, uint32_t b1) {
    asm volatile("mma.sync.aligned.m16n8k16.row.col.f32.bf16.bf16.f32 "
        "{%0,%1,%2,%3}, {%4,%5,%6,%7}, {%8,%9}, {%0,%1,%2,%3};"
        : "+f"(c[0]), "+f"(c[1]), "+f"(c[2]), "+f"(c[3])
        : "r"(a[0]), "r"(a[1]), "r"(a[2]), "r"(a[3]), "r"(b0), "r"(b1));
}
__device__ __forceinline__ void mma16816h(float* c, const uint32_t* a, uint32_t b0, uint32_t b1) {
    asm volatile("mma.sync.aligned.m16n8k16.row.col.f32.f16.f16.f32 "
        "{%0,%1,%2,%3}, {%4,%5,%6,%7}, {%8,%9}, {%0,%1,%2,%3};"
        : "+f"(c[0]), "+f"(c[1]), "+f"(c[2]), "+f"(c[3])
        : "r"(a[0]), "r"(a[1]), "r"(a[2]), "r"(a[3]), "r"(b0), "r"(b1));
}
// bf16x2 pack/unpack
__device__ __forceinline__ uint32_t pkbf(float lo, float hi) {
    uint32_t r;
    asm("cvt.rn.bf16x2.f32 %0, %1, %2;" : "=r"(r) : "f"(hi), "f"(lo));
    return r;
}
__device__ __forceinline__ float bflo(uint32_t u) { return __uint_as_float(u << 16); }
__device__ __forceinline__ float bfhi(uint32_t u) { return __uint_as_float(u & 0xFFFF0000u); }
__device__ __forceinline__ void split2(float v0, float v1, uint32_t& hi, uint32_t& lo) {
    hi = pkbf(v0, v1);
    lo = pkbf(v0 - bflo(hi), v1 - bfhi(hi));
}
// fp16x2 pack/unpack
__device__ __forceinline__ uint32_t pkh(float lo, float hi) {
    uint32_t r;
    asm("cvt.rn.f16x2.f32 %0, %1, %2;" : "=r"(r) : "f"(hi), "f"(lo));
    return r;
}
__device__ __forceinline__ float hlo(uint32_t u) {
    return __half2float(__ushort_as_half((unsigned short)(u & 0xFFFF)));
}
__device__ __forceinline__ float hhi(uint32_t u) {
    return __half2float(__ushort_as_half((unsigned short)(u >> 16)));
}
__device__ __forceinline__ void split2h(float v0, float v1, uint32_t& hi, uint32_t& lo) {
    hi = pkh(v0, v1);
    lo = pkh(v0 - hlo(hi), v1 - hhi(hi));
}

// fast exp on FMA/ALU pipes (x <= 0 expected; clamped)
__device__ __forceinline__ float fexp(float x) {
    float y = fmaxf(x, -80.0f) * 1.4426950408889634f;
    float t = y + 12582912.0f;
    int e = (__float_as_int(t) & 0x7FFFFF) - 0x400000;
    float f = y - (t - 12582912.0f);
    float p =      1.3333558146428443e-3f;
    p = fmaf(p, f, 9.6181291076284772e-3f);
    p = fmaf(p, f, 5.5504108664798463e-2f);
    p = fmaf(p, f, 2.4022650695910072e-1f);
    p = fmaf(p, f, 6.9314718055994531e-1f);
    p = fmaf(p, f, 1.0f);
    return __int_as_float(__float_as_int(p) + (e << 23));
}

// ---------------- RoPE table ----------------
__global__ void rope_table_kernel() {
    int idx = blockIdx.x * blockDim.x + threadIdx.x;
    if (idx >= SS * 32) return;
    int pos = idx >> 5;
    int i = idx & 31;
    float inv = powf(10000.0f, -((float)(2 * i)) / 64.0f);
    float t = (float)pos * inv;
    g_cos[idx] = cosf(t);
    g_sin[idx] = sinf(t);
}

// ---------------- fp32 -> fp16 converters ----------------
// mode 0: hidden -> gA16h/gA16l (split). mode 1: Wqkv -> gW16. mode 2: Wout -> gWo16.
__global__ void cvt16_kernel(const float* __restrict__ src, int n, int mode) {
    int i = (blockIdx.x * blockDim.x + threadIdx.x) * 4;
    if (i >= n) return;
    float4 v = *(const float4*)&src[i];
    uint32_t h01, h23, l01, l23;
    split2h(v.x, v.y, h01, l01);
    split2h(v.z, v.w, h23, l23);
    if (mode == 0) {
        *(uint32_t*)&gA16h[i]     = h01;
        *(uint32_t*)&gA16h[i + 2] = h23;
        *(uint32_t*)&gA16l[i]     = l01;
        *(uint32_t*)&gA16l[i + 2] = l23;
    } else if (mode == 1) {
        *(uint32_t*)&gW16[i]     = h01;
        *(uint32_t*)&gW16[i + 2] = h23;
    } else {
        *(uint32_t*)&gWo16[i]     = h01;
        *(uint32_t*)&gWo16[i + 2] = h23;
    }
}

// ---------------- unified fp16 2-product GEMM ----------------
// C = (Ah+Al) * B^T, fp16 operands, fp32 accum. CTA 128x128, 8 warps 32x64,
// K-chunk 32, 3-stage cp.async pipeline. Stage: Ah@0, Al@10240, B@20480 (30720B).
// mode 1: A=hidden16, B=Wqkv16, RoPE/scatter epilogue. mode 0: A=X16, B=Wout16, write C.
#define GEMM16_SMEM (3 * 30720)

__global__ __launch_bounds__(256, 2) void gemm16(float* __restrict__ C, int mode)
{
    extern __shared__ __align__(128) char sm[];
    const uint32_t sb = smem_u32(sm);
    const int t = threadIdx.x;
    const int lane = t & 31, warp = t >> 5;
    const int wm = warp & 3, wn = warp >> 2;
    const int rowA0 = blockIdx.y * 128;
    const int colB0 = blockIdx.x * 128;

    const __half *Abase, *Albase, *Bbase;
    if (mode == 1) {
        Abase = gA16h + (size_t)rowA0 * 1024;
        Albase = gA16l + (size_t)rowA0 * 1024;
        Bbase = gW16 + (size_t)colB0 * 1024;
    } else {
        Abase = gX16h + (size_t)rowA0 * 1024;
        Albase = gX16l + (size_t)rowA0 * 1024;
        Bbase = gWo16 + (size_t)colB0 * 1024;
    }

    float acc[2][8][4];
#pragma unroll
    for (int i = 0; i < 2; i++)
#pragma unroll
        for (int j = 0; j < 8; j++)
#pragma unroll
            for (int k = 0; k < 4; k++) acc[i][j][k] = 0.f;

    const int r0l = t >> 2, cb = t & 3;
    const int arow = (lane & 15);
    const int acol8 = (lane >> 4) * 8;
    const int quad = lane >> 3;
    const int brow_in = (quad >> 1) * 8 + (lane & 7);
    const int bcol8 = (quad & 1) * 8;

#define GPREFETCH(s) do {                                                       \
    const uint32_t _sbuf = sb + ((s) % 3) * 30720;                              \
    const int _k0 = (s) * 32;                                                   \
    _Pragma("unroll")                                                           \
    for (int _i = 0; _i < 2; _i++) {                                            \
        const int _row = r0l + _i * 64;                                         \
        const uint32_t _so = _sbuf + _row * 80 + cb * 16;                       \
        const size_t _go = (size_t)_row * 1024 + _k0 + cb * 8;                  \
        cp16(_so,          Abase + _go);                                        \
        cp16(_so + 10240,  Albase + _go);                                       \
        cp16(_so + 20480,  Bbase + _go);                                        \
    }                                                                           \
} while (0)

    GPREFETCH(0);
    asm volatile("cp.async.commit_group;");
    GPREFETCH(1);
    asm volatile("cp.async.commit_group;");

    for (int s = 0; s < 32; s++) {
        if (s + 2 < 32) {
            GPREFETCH(s + 2);
            asm volatile("cp.async.commit_group;");
            asm volatile("cp.async.wait_group 2;");
        } else if (s + 1 < 32) {
            asm volatile("cp.async.wait_group 1;");
        } else {
            asm volatile("cp.async.wait_group 0;");
        }
        __syncthreads();

        const uint32_t sbuf = sb + (s % 3) * 30720;
#pragma unroll
        for (int kk = 0; kk < 32; kk += 16) {
            uint32_t ah[2][4], al[2][4];
#pragma unroll
            for (int mt = 0; mt < 2; mt++) {
                uint32_t aa = sbuf + (wm * 32 + mt * 16 + arow) * 80 + (kk + acol8) * 2;
                ldmat4(ah[mt], aa);
                ldmat4(al[mt], aa + 10240);
            }
#pragma unroll
            for (int ntp = 0; ntp < 4; ntp++) {
                uint32_t ba = sbuf + 20480 + (wn * 64 + ntp * 16 + brow_in) * 80 + (kk + bcol8) * 2;
                uint32_t bh[4];
                ldmat4(bh, ba);
                // hi pass: 4 independent accumulators
                mma16816h(acc[0][2 * ntp],     ah[0], bh[0], bh[1]);
                mma16816h(acc[1][2 * ntp],     ah[1], bh[0], bh[1]);
                mma16816h(acc[0][2 * ntp + 1], ah[0], bh[2], bh[3]);
                mma16816h(acc[1][2 * ntp + 1], ah[1], bh[2], bh[3]);
                // lo pass: dependent reuse at distance 4
                mma16816h(acc[0][2 * ntp],     al[0], bh[0], bh[1]);
                mma16816h(acc[1][2 * ntp],     al[1], bh[0], bh[1]);
                mma16816h(acc[0][2 * ntp + 1], al[0], bh[2], bh[3]);
                mma16816h(acc[1][2 * ntp + 1], al[1], bh[2], bh[3]);
            }
        }
        __syncthreads();
    }
#undef GPREFETCH

    // ---------------- epilogue ----------------
    const int g = lane >> 2, tq = lane & 3;
#pragma unroll
    for (int mt = 0; mt < 2; mt++) {
#pragma unroll
        for (int nt = 0; nt < 8; nt++) {
            const int col = colB0 + wn * 64 + nt * 8 + tq * 2;
#pragma unroll
            for (int hr = 0; hr < 2; hr++) {
                const int row = rowA0 + wm * 32 + mt * 16 + g + hr * 8;
                const float v0 = acc[mt][nt][hr * 2];
                const float v1 = acc[mt][nt][hr * 2 + 1];
                if (mode == 0) {
                    *(float2*)&C[(size_t)row * 1024 + col] = make_float2(v0, v1);
                } else {
                    const int b = row >> 10, srow = row & 1023;
                    const int part = col >> 10, rem = col & 1023;
                    const int h = rem >> 6, d = rem & 63;
                    const size_t bhbase = (size_t)(b * NH + h) << 16;
                    if (part == 2) {
                        uint32_t hi, lo;
                        split2(v0, v1, hi, lo);
                        gVth[bhbase + (size_t)d * 1024 + srow]       = __ushort_as_bfloat16((unsigned short)(hi & 0xFFFF));
                        gVth[bhbase + (size_t)(d + 1) * 1024 + srow] = __ushort_as_bfloat16((unsigned short)(hi >> 16));
                        gVtl[bhbase + (size_t)d * 1024 + srow]       = __ushort_as_bfloat16((unsigned short)(lo & 0xFFFF));
                        gVtl[bhbase + (size_t)(d + 1) * 1024 + srow] = __ushort_as_bfloat16((unsigned short)(lo >> 16));
                    } else {
                        const float co = g_cos[(srow << 5) + (d >> 1)];
                        const float si = g_sin[(srow << 5) + (d >> 1)];
                        float o0 = v0 * co - v1 * si;
                        float o1 = v1 * co + v0 * si;
                        const size_t gb = bhbase + ((size_t)srow << 6) + d;
                        uint32_t hi, lo;
                        if (part == 0) {
                            o0 *= 0.125f; o1 *= 0.125f;
                            split2(o0, o1, hi, lo);
                            *(uint32_t*)&gQh[gb] = hi;
                            *(uint32_t*)&gQl[gb] = lo;
                        } else {
                            split2(o0, o1, hi, lo);
                            *(uint32_t*)&gKh[gb] = hi;
                            *(uint32_t*)&gKl[gb] = lo;
                        }
                    }
                }
            }
        }
    }
}

// ---------------- tensorized flash attention (bf16 3-product, fp16-split X out) ----------------
#define ATT_SMEM (18432 + 2 * 36864)

__global__ __launch_bounds__(128) void attn_kernel()
{
    extern __shared__ __align__(128) char sm[];
    const uint32_t sb = smem_u32(sm);
    const int t = threadIdx.x, lane = t & 31, w = t >> 5;
    const int qt = blockIdx.x, bh = blockIdx.y;

    const __nv_bfloat16* Qh_p  = gQh  + (size_t)bh * 65536 + qt * 4096;
    const __nv_bfloat16* Ql_p  = gQl  + (size_t)bh * 65536 + qt * 4096;
    const __nv_bfloat16* Kh_b  = gKh  + (size_t)bh * 65536;
    const __nv_bfloat16* Kl_b  = gKl  + (size_t)bh * 65536;
    const __nv_bfloat16* Vth_b = gVth + (size_t)bh * 65536;
    const __nv_bfloat16* Vtl_b = gVtl + (size_t)bh * 65536;

    const int arow = lane & 15, acol8 = (lane >> 4) * 8;
    const int quad = lane >> 3;
    const int brow = (quad >> 1) * 8 + (lane & 7);
    const int bcol8 = (quad & 1) * 8;
    const int g = lane >> 2, tq = lane & 3;
    const int row0 = w * 16 + g;

#pragma unroll
    for (int i = 0; i < 8; i++) {
        int ch = t + i * 128;
        int tile = ch >> 9;
        int r = (ch >> 3) & 63, cbk = ch & 7;
        cp16(sb + tile * 9216 + r * 144 + cbk * 16,
             (tile ? Ql_p : Qh_p) + r * 64 + cbk * 8);
    }
    asm volatile("cp.async.commit_group;");

#define LOAD_STAGE(KT) do {                                                   \
    const uint32_t _st = sb + 18432 + ((KT) & 1) * 36864;                     \
    _Pragma("unroll")                                                         \
    for (int _i = 0; _i < 4; _i++) {                                          \
        int _ch = t + _i * 128;                                               \
        int _r = _ch >> 3, _cb = _ch & 7;                                     \
        uint32_t _off = _r * 144 + _cb * 16;                                  \
        size_t _gk = (size_t)(KT) * 4096 + _r * 64 + _cb * 8;                 \
        size_t _gv = (size_t)_r * 1024 + (KT) * 64 + _cb * 8;                 \
        cp16(_st + _off,         Kh_b + _gk);                                 \
        cp16(_st + 9216 + _off,  Kl_b + _gk);                                 \
        cp16(_st + 18432 + _off, Vth_b + _gv);                                \
        cp16(_st + 27648 + _off, Vtl_b + _gv);                                \
    }                                                                         \
} while (0)

    LOAD_STAGE(0);
    asm volatile("cp.async.commit_group;");

    float m0 = -1e30f, m1 = -1e30f, l0 = 0.f, l1 = 0.f;
    float o[8][4];
#pragma unroll
    for (int nt = 0; nt < 8; nt++)
#pragma unroll
        for (int j = 0; j < 4; j++) o[nt][j] = 0.f;
    uint32_t qh[4][4], ql[4][4];

    for (int kt = 0; kt <= qt; kt++) {
        if (kt + 1 <= qt) {
            LOAD_STAGE(kt + 1);
            asm volatile("cp.async.commit_group;");
            asm volatile("cp.async.wait_group 1;");
        } else {
            asm volatile("cp.async.wait_group 0;");
        }
        __syncthreads();

        if (kt == 0) {
#pragma unroll
            for (int c = 0; c < 4; c++) {
                uint32_t qa = sb + (w * 16 + arow) * 144 + (c * 16 + acol8) * 2;
                ldmat4(qh[c], qa);
                ldmat4(ql[c], qa + 9216);
            }
        }

        const uint32_t ST  = sb + 18432 + (kt & 1) * 36864;
        const uint32_t KH = ST, VTH = ST + 18432;

        float sc[8][4];
#pragma unroll
        for (int nt = 0; nt < 8; nt++)
#pragma unroll
            for (int j = 0; j < 4; j++) sc[nt][j] = 0.f;

#pragma unroll
        for (int np = 0; np < 4; np++) {
#pragma unroll
            for (int c = 0; c < 4; c++) {
                uint32_t kh4[4], kl4[4];
                uint32_t ka = KH + (np * 16 + brow) * 144 + (c * 16 + bcol8) * 2;
                ldmat4(kh4, ka);
                ldmat4(kl4, ka + 9216);
                mma16816(sc[2 * np],     qh[c], kh4[0], kh4[1]);
                mma16816(sc[2 * np],     qh[c], kl4[0], kl4[1]);
                mma16816(sc[2 * np],     ql[c], kh4[0], kh4[1]);
                mma16816(sc[2 * np + 1], qh[c], kh4[2], kh4[3]);
                mma16816(sc[2 * np + 1], qh[c], kl4[2], kl4[3]);
                mma16816(sc[2 * np + 1], ql[c], kh4[2], kh4[3]);
            }
        }

        if (kt == qt) {
#pragma unroll
            for (int nt = 0; nt < 8; nt++) {
                int cbase = nt * 8 + tq * 2;
                if (cbase     > row0)     sc[nt][0] = -1e30f;
                if (cbase + 1 > row0)     sc[nt][1] = -1e30f;
                if (cbase     > row0 + 8) sc[nt][2] = -1e30f;
                if (cbase + 1 > row0 + 8) sc[nt][3] = -1e30f;
            }
        }

        float mt0 = sc[0][0], mt1 = sc[0][2];
#pragma unroll
        for (int nt = 0; nt < 8; nt++) {
            mt0 = fmaxf(mt0, fmaxf(sc[nt][0], sc[nt][1]));
            mt1 = fmaxf(mt1, fmaxf(sc[nt][2], sc[nt][3]));
        }
        mt0 = fmaxf(mt0, __shfl_xor_sync(0xffffffffu, mt0, 1));
        mt0 = fmaxf(mt0, __shfl_xor_sync(0xffffffffu, mt0, 2));
        mt1 = fmaxf(mt1, __shfl_xor_sync(0xffffffffu, mt1, 1));
        mt1 = fmaxf(mt1, __shfl_xor_sync(0xffffffffu, mt1, 2));
        float mn0 = fmaxf(m0, mt0), mn1 = fmaxf(m1, mt1);
        float a0 = fexp(m0 - mn0), a1 = fexp(m1 - mn1);
        m0 = mn0; m1 = mn1;
        float s0 = 0.f, s1 = 0.f;
#pragma unroll
        for (int nt = 0; nt < 8; nt++) {
            sc[nt][0] = fexp(sc[nt][0] - m0); s0 += sc[nt][0];
            sc[nt][1] = fexp(sc[nt][1] - m0); s0 += sc[nt][1];
            sc[nt][2] = fexp(sc[nt][2] - m1); s1 += sc[nt][2];
            sc[nt][3] = fexp(sc[nt][3] - m1); s1 += sc[nt][3];
        }
        s0 += __shfl_xor_sync(0xffffffffu, s0, 1);
        s0 += __shfl_xor_sync(0xffffffffu, s0, 2);
        s1 += __shfl_xor_sync(0xffffffffu, s1, 1);
        s1 += __shfl_xor_sync(0xffffffffu, s1, 2);
        l0 = l0 * a0 + s0;
        l1 = l1 * a1 + s1;
#pragma unroll
        for (int nt = 0; nt < 8; nt++) {
            o[nt][0] *= a0; o[nt][1] *= a0;
            o[nt][2] *= a1; o[nt][3] *= a1;
        }

#pragma unroll
        for (int c = 0; c < 4; c++) {
            const float* pa = sc[2 * c];
            const float* pb = sc[2 * c + 1];
            uint32_t pah[4], pal[4];
            pah[0] = pkbf(pa[0], pa[1]);
            pah[1] = pkbf(pa[2], pa[3]);
            pah[2] = pkbf(pb[0], pb[1]);
            pah[3] = pkbf(pb[2], pb[3]);
            pal[0] = pkbf(pa[0] - bflo(pah[0]), pa[1] - bfhi(pah[0]));
            pal[1] = pkbf(pa[2] - bflo(pah[1]), pa[3] - bfhi(pah[1]));
            pal[2] = pkbf(pb[0] - bflo(pah[2]), pb[1] - bfhi(pah[2]));
            pal[3] = pkbf(pb[2] - bflo(pah[3]), pb[3] - bfhi(pah[3]));
#pragma unroll
            for (int np = 0; np < 4; np++) {
                uint32_t vh4[4], vl4[4];
                uint32_t va = VTH + (np * 16 + brow) * 144 + (c * 16 + bcol8) * 2;
                ldmat4(vh4, va);
                ldmat4(vl4, va + 9216);
                mma16816(o[2 * np],     pah, vh4[0], vh4[1]);
                mma16816(o[2 * np],     pah, vl4[0], vl4[1]);
                mma16816(o[2 * np],     pal, vh4[0], vh4[1]);
                mma16816(o[2 * np + 1], pah, vh4[2], vh4[3]);
                mma16816(o[2 * np + 1], pah, vl4[2], vl4[3]);
                mma16816(o[2 * np + 1], pal, vh4[2], vh4[3]);
            }
        }
        __syncthreads();
    }
#undef LOAD_STAGE

    // ---- epilogue: X = O / l, write split fp16 ----
    const float il0 = 1.0f / l0, il1 = 1.0f / l1;
    const int b = bh >> 4, h = bh & 15;
    const int sr0 = qt * 64 + w * 16 + g;
    const size_t base0 = ((size_t)((b << 10) + sr0)) * 1024 + h * 64;
    const size_t base1 = base0 + 8 * 1024;
#pragma unroll
    for (int nt = 0; nt < 8; nt++) {
        const int d = nt * 8 + tq * 2;
        uint32_t hi, lo;
        split2h(o[nt][0] * il0, o[nt][1] * il0, hi, lo);
        *(uint32_t*)&gX16h[base0 + d] = hi;
        *(uint32_t*)&gX16l[base0 + d] = lo;
        split2h(o[nt][2] * il1, o[nt][3] * il1, hi, lo);
        *(uint32_t*)&gX16h[base1 + d] = hi;
        *(uint32_t*)&gX16l[base1 + d] = lo;
    }
}

// ---------------- launch ----------------
extern "C" void kernel_launch(void* const* d_in, const int* in_sizes, int n_in,
                              void* d_out, int out_size)
{
    const float* hidden = (const float*)d_in[0];
    const float* Wqkv = (const float*)d_in[3];
    const float* Wout = (const float*)d_in[4];
    float* out = (float*)d_out;

    cudaFuncSetAttribute(gemm16, cudaFuncAttributeMaxDynamicSharedMemorySize, GEMM16_SMEM);
    cudaFuncSetAttribute(attn_kernel, cudaFuncAttributeMaxDynamicSharedMemorySize, ATT_SMEM);

    rope_table_kernel<<<128, 256>>>();                      // launch 0
    cvt16_kernel<<<4096, 256>>>(hidden, 4194304, 0);        // launch 1
    cvt16_kernel<<<3072, 256>>>(Wqkv, 3145728, 1);          // launch 2
    gemm16<<<dim3(24, 32), 256, GEMM16_SMEM>>>(nullptr, 1); // launch 3 (ncu slot): QKV
    cvt16_kernel<<<1024, 256>>>(Wout, 1048576, 2);          // launch 4
    attn_kernel<<<dim3(16, 64), 128, ATT_SMEM>>>();         // launch 5
    gemm16<<<dim3(8, 32), 256, GEMM16_SMEM>>>(out, 0);      // launch 6: out-proj
}

// round 11
// speedup vs baseline: 4.4169x; 1.3156x over previous
#include <cuda_runtime.h>
#include <cuda_bf16.h>
#include <cuda_fp16.h>
#include <cstdint>

#define BB 4
#define SS 1024
#define DM 1024
#define NH 16
#define HD 64

// ---------------- scratch (__device__ globals; no runtime allocation) ----------------
__device__ float g_cos[SS*32];
__device__ float g_sin[SS*32];

__device__ __half gA16h[4194304];                      // hidden fp16
__device__ __half gW16[3145728];                       // Wqkv fp16
__device__ __half gWo16[1048576];                      // Wout fp16
__device__ __half gX16h[4194304];                      // attn output fp16

// attention operands, split bf16, [bh][...]
__device__ __nv_bfloat16 gQh[4194304], gQl[4194304];   // [bh][s][64], pre-scaled 0.125, RoPE'd
__device__ __nv_bfloat16 gKh[4194304], gKl[4194304];   // [bh][s][64], RoPE'd
__device__ __nv_bfloat16 gVth[4194304], gVtl[4194304]; // [bh][d][s]  (transposed V)

// ---------------- helpers ----------------
__device__ __forceinline__ uint32_t smem_u32(const void* p) {
    uint32_t a;
    asm("{ .reg .u64 t; cvta.to.shared.u64 t, %1; cvt.u32.u64 %0, t; }" : "=r"(a) : "l"(p));
    return a;
}
__device__ __forceinline__ void cp16(uint32_t so, const void* g) {
    asm volatile("cp.async.cg.shared.global [%0], [%1], 16;" :: "r"(so), "l"(g));
}
__device__ __forceinline__ void ldmat4(uint32_t* r, uint32_t addr) {
    asm volatile("ldmatrix.sync.aligned.m8n8.x4.shared.b16 {%0,%1,%2,%3}, [%4];"
        : "=r"(r[0]), "=r"(r[1]), "=r"(r[2]), "=r"(r[3]) : "r"(addr));
}
__device__ __forceinline__ void mma16816(float* c, const uint32_t* a, uint32_t b0, uint32_t b1) {
    asm volatile("mma.sync.aligned.m16n8k16.row.col.f32.bf16.bf16.f32 "
        "{%0,%1,%2,%3}, {%4,%5,%6,%7}, {%8,%9}, {%0,%1,%2,%3};"
        : "+f"(c[0]), "+f"(c[1]), "+f"(c[2]), "+f"(c[3])
        : "r"(a[0]), "r"(a[1]), "r"(a[2]), "r"(a[3]), "r"(b0), "r"(b1));
}
__device__ __forceinline__ void mma16816h(float* c, const uint32_t* a, uint32_t b0, uint32_t b1) {
    asm volatile("mma.sync.aligned.m16n8k16.row.col.f32.f16.f16.f32 "
        "{%0,%1,%2,%3}, {%4,%5,%6,%7}, {%8,%9}, {%0,%1,%2,%3};"
        : "+f"(c[0]), "+f"(c[1]), "+f"(c[2]), "+f"(c[3])
        : "r"(a[0]), "r"(a[1]), "r"(a[2]), "r"(a[3]), "r"(b0), "r"(b1));
}
// bf16x2 pack/unpack
__device__ __forceinline__ uint32_t pkbf(float lo, float hi) {
    uint32_t r;
    asm("cvt.rn.bf16x2.f32 %0, %1, %2;" : "=r"(r) : "f"(hi), "f"(lo));
    return r;
}
__device__ __forceinline__ float bflo(uint32_t u) { return __uint_as_float(u << 16); }
__device__ __forceinline__ float bfhi(uint32_t u) { return __uint_as_float(u & 0xFFFF0000u); }
__device__ __forceinline__ void split2(float v0, float v1, uint32_t& hi, uint32_t& lo) {
    hi = pkbf(v0, v1);
    lo = pkbf(v0 - bflo(hi), v1 - bfhi(hi));
}
// fp16x2 pack
__device__ __forceinline__ uint32_t pkh(float lo, float hi) {
    uint32_t r;
    asm("cvt.rn.f16x2.f32 %0, %1, %2;" : "=r"(r) : "f"(hi), "f"(lo));
    return r;
}

// fast exp on FMA/ALU pipes (x <= 0 expected; clamped)
__device__ __forceinline__ float fexp(float x) {
    float y = fmaxf(x, -80.0f) * 1.4426950408889634f;
    float t = y + 12582912.0f;
    int e = (__float_as_int(t) & 0x7FFFFF) - 0x400000;
    float f = y - (t - 12582912.0f);
    float p =      1.3333558146428443e-3f;
    p = fmaf(p, f, 9.6181291076284772e-3f);
    p = fmaf(p, f, 5.5504108664798463e-2f);
    p = fmaf(p, f, 2.4022650695910072e-1f);
    p = fmaf(p, f, 6.9314718055994531e-1f);
    p = fmaf(p, f, 1.0f);
    return __int_as_float(__float_as_int(p) + (e << 23));
}

// ---------------- RoPE table ----------------
__global__ void rope_table_kernel() {
    int idx = blockIdx.x * blockDim.x + threadIdx.x;
    if (idx >= SS * 32) return;
    int pos = idx >> 5;
    int i = idx & 31;
    float inv = powf(10000.0f, -((float)(2 * i)) / 64.0f);
    float t = (float)pos * inv;
    g_cos[idx] = cosf(t);
    g_sin[idx] = sinf(t);
}

// ---------------- fp32 -> fp16 converter ----------------
// mode 0: hidden -> gA16h. mode 1: Wqkv -> gW16. mode 2: Wout -> gWo16.
__global__ void cvt16_kernel(const float* __restrict__ src, int n, int mode) {
    int i = (blockIdx.x * blockDim.x + threadIdx.x) * 4;
    if (i >= n) return;
    float4 v = *(const float4*)&src[i];
    uint32_t h01 = pkh(v.x, v.y);
    uint32_t h23 = pkh(v.z, v.w);
    __half* dst = (mode == 0) ? gA16h : (mode == 1) ? gW16 : gWo16;
    *(uint32_t*)&dst[i]     = h01;
    *(uint32_t*)&dst[i + 2] = h23;
}

// ---------------- single-product fp16 GEMM ----------------
// C = A * B^T, fp16 operands, fp32 accum. CTA 128x128, 8 warps 32x64,
// K-chunk 32, 3-stage cp.async pipeline. Stage: A@0, B@10240 (20480B).
// mode 1: A=hidden16, B=Wqkv16, RoPE/scatter epilogue. mode 0: A=X16, B=Wout16, write C.
#define GEMM16_SMEM (3 * 20480)

__global__ __launch_bounds__(256, 2) void gemm16(float* __restrict__ C, int mode)
{
    extern __shared__ __align__(128) char sm[];
    const uint32_t sb = smem_u32(sm);
    const int t = threadIdx.x;
    const int lane = t & 31, warp = t >> 5;
    const int wm = warp & 3, wn = warp >> 2;
    const int rowA0 = blockIdx.y * 128;
    const int colB0 = blockIdx.x * 128;

    const __half *Abase, *Bbase;
    if (mode == 1) {
        Abase = gA16h + (size_t)rowA0 * 1024;
        Bbase = gW16 + (size_t)colB0 * 1024;
    } else {
        Abase = gX16h + (size_t)rowA0 * 1024;
        Bbase = gWo16 + (size_t)colB0 * 1024;
    }

    float acc[2][8][4];
#pragma unroll
    for (int i = 0; i < 2; i++)
#pragma unroll
        for (int j = 0; j < 8; j++)
#pragma unroll
            for (int k = 0; k < 4; k++) acc[i][j][k] = 0.f;

    const int r0l = t >> 2, cb = t & 3;
    const int arow = (lane & 15);
    const int acol8 = (lane >> 4) * 8;
    const int quad = lane >> 3;
    const int brow_in = (quad >> 1) * 8 + (lane & 7);
    const int bcol8 = (quad & 1) * 8;

#define GPREFETCH(s) do {                                                       \
    const uint32_t _sbuf = sb + ((s) % 3) * 20480;                              \
    const int _k0 = (s) * 32;                                                   \
    _Pragma("unroll")                                                           \
    for (int _i = 0; _i < 2; _i++) {                                            \
        const int _row = r0l + _i * 64;                                         \
        const uint32_t _so = _sbuf + _row * 80 + cb * 16;                       \
        const size_t _go = (size_t)_row * 1024 + _k0 + cb * 8;                  \
        cp16(_so,          Abase + _go);                                        \
        cp16(_so + 10240,  Bbase + _go);                                        \
    }                                                                           \
} while (0)

    GPREFETCH(0);
    asm volatile("cp.async.commit_group;");
    GPREFETCH(1);
    asm volatile("cp.async.commit_group;");

    for (int s = 0; s < 32; s++) {
        if (s + 2 < 32) {
            GPREFETCH(s + 2);
            asm volatile("cp.async.commit_group;");
            asm volatile("cp.async.wait_group 2;");
        } else if (s + 1 < 32) {
            asm volatile("cp.async.wait_group 1;");
        } else {
            asm volatile("cp.async.wait_group 0;");
        }
        __syncthreads();

        const uint32_t sbuf = sb + (s % 3) * 20480;
#pragma unroll
        for (int kk = 0; kk < 32; kk += 16) {
            uint32_t ah[2][4];
#pragma unroll
            for (int mt = 0; mt < 2; mt++) {
                uint32_t aa = sbuf + (wm * 32 + mt * 16 + arow) * 80 + (kk + acol8) * 2;
                ldmat4(ah[mt], aa);
            }
#pragma unroll
            for (int ntp = 0; ntp < 4; ntp++) {
                uint32_t ba = sbuf + 10240 + (wn * 64 + ntp * 16 + brow_in) * 80 + (kk + bcol8) * 2;
                uint32_t bh[4];
                ldmat4(bh, ba);
                mma16816h(acc[0][2 * ntp],     ah[0], bh[0], bh[1]);
                mma16816h(acc[1][2 * ntp],     ah[1], bh[0], bh[1]);
                mma16816h(acc[0][2 * ntp + 1], ah[0], bh[2], bh[3]);
                mma16816h(acc[1][2 * ntp + 1], ah[1], bh[2], bh[3]);
            }
        }
        __syncthreads();
    }
#undef GPREFETCH

    // ---------------- epilogue ----------------
    const int g = lane >> 2, tq = lane & 3;
#pragma unroll
    for (int mt = 0; mt < 2; mt++) {
#pragma unroll
        for (int nt = 0; nt < 8; nt++) {
            const int col = colB0 + wn * 64 + nt * 8 + tq * 2;
#pragma unroll
            for (int hr = 0; hr < 2; hr++) {
                const int row = rowA0 + wm * 32 + mt * 16 + g + hr * 8;
                const float v0 = acc[mt][nt][hr * 2];
                const float v1 = acc[mt][nt][hr * 2 + 1];
                if (mode == 0) {
                    *(float2*)&C[(size_t)row * 1024 + col] = make_float2(v0, v1);
                } else {
                    const int b = row >> 10, srow = row & 1023;
                    const int part = col >> 10, rem = col & 1023;
                    const int h = rem >> 6, d = rem & 63;
                    const size_t bhbase = (size_t)(b * NH + h) << 16;
                    if (part == 2) {
                        uint32_t hi, lo;
                        split2(v0, v1, hi, lo);
                        gVth[bhbase + (size_t)d * 1024 + srow]       = __ushort_as_bfloat16((unsigned short)(hi & 0xFFFF));
                        gVth[bhbase + (size_t)(d + 1) * 1024 + srow] = __ushort_as_bfloat16((unsigned short)(hi >> 16));
                        gVtl[bhbase + (size_t)d * 1024 + srow]       = __ushort_as_bfloat16((unsigned short)(lo & 0xFFFF));
                        gVtl[bhbase + (size_t)(d + 1) * 1024 + srow] = __ushort_as_bfloat16((unsigned short)(lo >> 16));
                    } else {
                        const float co = g_cos[(srow << 5) + (d >> 1)];
                        const float si = g_sin[(srow << 5) + (d >> 1)];
                        float o0 = v0 * co - v1 * si;
                        float o1 = v1 * co + v0 * si;
                        const size_t gb = bhbase + ((size_t)srow << 6) + d;
                        uint32_t hi, lo;
                        if (part == 0) {
                            o0 *= 0.125f; o1 *= 0.125f;
                            split2(o0, o1, hi, lo);
                            *(uint32_t*)&gQh[gb] = hi;
                            *(uint32_t*)&gQl[gb] = lo;
                        } else {
                            split2(o0, o1, hi, lo);
                            *(uint32_t*)&gKh[gb] = hi;
                            *(uint32_t*)&gKl[gb] = lo;
                        }
                    }
                }
            }
        }
    }
}

// ---------------- tensorized flash attention (bf16 3-product, fp16 X out) ----------------
#define ATT_SMEM (18432 + 2 * 36864)

__global__ __launch_bounds__(128) void attn_kernel()
{
    extern __shared__ __align__(128) char sm[];
    const uint32_t sb = smem_u32(sm);
    const int t = threadIdx.x, lane = t & 31, w = t >> 5;
    const int qt = blockIdx.x, bh = blockIdx.y;

    const __nv_bfloat16* Qh_p  = gQh  + (size_t)bh * 65536 + qt * 4096;
    const __nv_bfloat16* Ql_p  = gQl  + (size_t)bh * 65536 + qt * 4096;
    const __nv_bfloat16* Kh_b  = gKh  + (size_t)bh * 65536;
    const __nv_bfloat16* Kl_b  = gKl  + (size_t)bh * 65536;
    const __nv_bfloat16* Vth_b = gVth + (size_t)bh * 65536;
    const __nv_bfloat16* Vtl_b = gVtl + (size_t)bh * 65536;

    const int arow = lane & 15, acol8 = (lane >> 4) * 8;
    const int quad = lane >> 3;
    const int brow = (quad >> 1) * 8 + (lane & 7);
    const int bcol8 = (quad & 1) * 8;
    const int g = lane >> 2, tq = lane & 3;
    const int row0 = w * 16 + g;

#pragma unroll
    for (int i = 0; i < 8; i++) {
        int ch = t + i * 128;
        int tile = ch >> 9;
        int r = (ch >> 3) & 63, cbk = ch & 7;
        cp16(sb + tile * 9216 + r * 144 + cbk * 16,
             (tile ? Ql_p : Qh_p) + r * 64 + cbk * 8);
    }
    asm volatile("cp.async.commit_group;");

#define LOAD_STAGE(KT) do {                                                   \
    const uint32_t _st = sb + 18432 + ((KT) & 1) * 36864;                     \
    _Pragma("unroll")                                                         \
    for (int _i = 0; _i < 4; _i++) {                                          \
        int _ch = t + _i * 128;                                               \
        int _r = _ch >> 3, _cb = _ch & 7;                                     \
        uint32_t _off = _r * 144 + _cb * 16;                                  \
        size_t _gk = (size_t)(KT) * 4096 + _r * 64 + _cb * 8;                 \
        size_t _gv = (size_t)_r * 1024 + (KT) * 64 + _cb * 8;                 \
        cp16(_st + _off,         Kh_b + _gk);                                 \
        cp16(_st + 9216 + _off,  Kl_b + _gk);                                 \
        cp16(_st + 18432 + _off, Vth_b + _gv);                                \
        cp16(_st + 27648 + _off, Vtl_b + _gv);                                \
    }                                                                         \
} while (0)

    LOAD_STAGE(0);
    asm volatile("cp.async.commit_group;");

    float m0 = -1e30f, m1 = -1e30f, l0 = 0.f, l1 = 0.f;
    float o[8][4];
#pragma unroll
    for (int nt = 0; nt < 8; nt++)
#pragma unroll
        for (int j = 0; j < 4; j++) o[nt][j] = 0.f;
    uint32_t qh[4][4], ql[4][4];

    for (int kt = 0; kt <= qt; kt++) {
        if (kt + 1 <= qt) {
            LOAD_STAGE(kt + 1);
            asm volatile("cp.async.commit_group;");
            asm volatile("cp.async.wait_group 1;");
        } else {
            asm volatile("cp.async.wait_group 0;");
        }
        __syncthreads();

        if (kt == 0) {
#pragma unroll
            for (int c = 0; c < 4; c++) {
                uint32_t qa = sb + (w * 16 + arow) * 144 + (c * 16 + acol8) * 2;
                ldmat4(qh[c], qa);
                ldmat4(ql[c], qa + 9216);
            }
        }

        const uint32_t ST  = sb + 18432 + (kt & 1) * 36864;
        const uint32_t KH = ST, VTH = ST + 18432;

        float sc[8][4];
#pragma unroll
        for (int nt = 0; nt < 8; nt++)
#pragma unroll
            for (int j = 0; j < 4; j++) sc[nt][j] = 0.f;

#pragma unroll
        for (int np = 0; np < 4; np++) {
#pragma unroll
            for (int c = 0; c < 4; c++) {
                uint32_t kh4[4], kl4[4];
                uint32_t ka = KH + (np * 16 + brow) * 144 + (c * 16 + bcol8) * 2;
                ldmat4(kh4, ka);
                ldmat4(kl4, ka + 9216);
                mma16816(sc[2 * np],     qh[c], kh4[0], kh4[1]);
                mma16816(sc[2 * np],     qh[c], kl4[0], kl4[1]);
                mma16816(sc[2 * np],     ql[c], kh4[0], kh4[1]);
                mma16816(sc[2 * np + 1], qh[c], kh4[2], kh4[3]);
                mma16816(sc[2 * np + 1], qh[c], kl4[2], kl4[3]);
                mma16816(sc[2 * np + 1], ql[c], kh4[2], kh4[3]);
            }
        }

        if (kt == qt) {
#pragma unroll
            for (int nt = 0; nt < 8; nt++) {
                int cbase = nt * 8 + tq * 2;
                if (cbase     > row0)     sc[nt][0] = -1e30f;
                if (cbase + 1 > row0)     sc[nt][1] = -1e30f;
                if (cbase     > row0 + 8) sc[nt][2] = -1e30f;
                if (cbase + 1 > row0 + 8) sc[nt][3] = -1e30f;
            }
        }

        float mt0 = sc[0][0], mt1 = sc[0][2];
#pragma unroll
        for (int nt = 0; nt < 8; nt++) {
            mt0 = fmaxf(mt0, fmaxf(sc[nt][0], sc[nt][1]));
            mt1 = fmaxf(mt1, fmaxf(sc[nt][2], sc[nt][3]));
        }
        mt0 = fmaxf(mt0, __shfl_xor_sync(0xffffffffu, mt0, 1));
        mt0 = fmaxf(mt0, __shfl_xor_sync(0xffffffffu, mt0, 2));
        mt1 = fmaxf(mt1, __shfl_xor_sync(0xffffffffu, mt1, 1));
        mt1 = fmaxf(mt1, __shfl_xor_sync(0xffffffffu, mt1, 2));
        float mn0 = fmaxf(m0, mt0), mn1 = fmaxf(m1, mt1);
        float a0 = fexp(m0 - mn0), a1 = fexp(m1 - mn1);
        m0 = mn0; m1 = mn1;
        float s0 = 0.f, s1 = 0.f;
#pragma unroll
        for (int nt = 0; nt < 8; nt++) {
            sc[nt][0] = fexp(sc[nt][0] - m0); s0 += sc[nt][0];
            sc[nt][1] = fexp(sc[nt][1] - m0); s0 += sc[nt][1];
            sc[nt][2] = fexp(sc[nt][2] - m1); s1 += sc[nt][2];
            sc[nt][3] = fexp(sc[nt][3] - m1); s1 += sc[nt][3];
        }
        s0 += __shfl_xor_sync(0xffffffffu, s0, 1);
        s0 += __shfl_xor_sync(0xffffffffu, s0, 2);
        s1 += __shfl_xor_sync(0xffffffffu, s1, 1);
        s1 += __shfl_xor_sync(0xffffffffu, s1, 2);
        l0 = l0 * a0 + s0;
        l1 = l1 * a1 + s1;
#pragma unroll
        for (int nt = 0; nt < 8; nt++) {
            o[nt][0] *= a0; o[nt][1] *= a0;
            o[nt][2] *= a1; o[nt][3] *= a1;
        }

#pragma unroll
        for (int c = 0; c < 4; c++) {
            const float* pa = sc[2 * c];
            const float* pb = sc[2 * c + 1];
            uint32_t pah[4], pal[4];
            pah[0] = pkbf(pa[0], pa[1]);
            pah[1] = pkbf(pa[2], pa[3]);
            pah[2] = pkbf(pb[0], pb[1]);
            pah[3] = pkbf(pb[2], pb[3]);
            pal[0] = pkbf(pa[0] - bflo(pah[0]), pa[1] - bfhi(pah[0]));
            pal[1] = pkbf(pa[2] - bflo(pah[1]), pa[3] - bfhi(pah[1]));
            pal[2] = pkbf(pb[0] - bflo(pah[2]), pb[1] - bfhi(pah[2]));
            pal[3] = pkbf(pb[2] - bflo(pah[3]), pb[3] - bfhi(pah[3]));
#pragma unroll
            for (int np = 0; np < 4; np++) {
                uint32_t vh4[4], vl4[4];
                uint32_t va = VTH + (np * 16 + brow) * 144 + (c * 16 + bcol8) * 2;
                ldmat4(vh4, va);
                ldmat4(vl4, va + 9216);
                mma16816(o[2 * np],     pah, vh4[0], vh4[1]);
                mma16816(o[2 * np],     pah, vl4[0], vl4[1]);
                mma16816(o[2 * np],     pal, vh4[0], vh4[1]);
                mma16816(o[2 * np + 1], pah, vh4[2], vh4[3]);
                mma16816(o[2 * np + 1], pah, vl4[2], vl4[3]);
                mma16816(o[2 * np + 1], pal, vh4[2], vh4[3]);
            }
        }
        __syncthreads();
    }
#undef LOAD_STAGE

    // ---- epilogue: X = O / l, write fp16 ----
    const float il0 = 1.0f / l0, il1 = 1.0f / l1;
    const int b = bh >> 4, h = bh & 15;
    const int sr0 = qt * 64 + w * 16 + g;
    const size_t base0 = ((size_t)((b << 10) + sr0)) * 1024 + h * 64;
    const size_t base1 = base0 + 8 * 1024;
#pragma unroll
    for (int nt = 0; nt < 8; nt++) {
        const int d = nt * 8 + tq * 2;
        *(uint32_t*)&gX16h[base0 + d] = pkh(o[nt][0] * il0, o[nt][1] * il0);
        *(uint32_t*)&gX16h[base1 + d] = pkh(o[nt][2] * il1, o[nt][3] * il1);
    }
}

// ---------------- launch ----------------
extern "C" void kernel_launch(void* const* d_in, const int* in_sizes, int n_in,
                              void* d_out, int out_size)
{
    const float* hidden = (const float*)d_in[0];
    const float* Wqkv = (const float*)d_in[3];
    const float* Wout = (const float*)d_in[4];
    float* out = (float*)d_out;

    cudaFuncSetAttribute(gemm16, cudaFuncAttributeMaxDynamicSharedMemorySize, GEMM16_SMEM);
    cudaFuncSetAttribute(attn_kernel, cudaFuncAttributeMaxDynamicSharedMemorySize, ATT_SMEM);

    rope_table_kernel<<<128, 256>>>();                      // launch 0
    cvt16_kernel<<<4096, 256>>>(hidden, 4194304, 0);        // launch 1
    cvt16_kernel<<<3072, 256>>>(Wqkv, 3145728, 1);          // launch 2
    gemm16<<<dim3(24, 32), 256, GEMM16_SMEM>>>(nullptr, 1); // launch 3 (ncu slot): QKV
    cvt16_kernel<<<1024, 256>>>(Wout, 1048576, 2);          // launch 4
    attn_kernel<<<dim3(16, 64), 128, ATT_SMEM>>>();         // launch 5
    gemm16<<<dim3(8, 32), 256, GEMM16_SMEM>>>(out, 0);      // launch 6: out-proj
}